// round 6
// baseline (speedup 1.0000x reference)
#include <cuda_runtime.h>
#include <cstdint>
#include <math.h>

#define N_NODES 50000
#define E_EDGES 800000
#define F_IN    128
#define HID     96
#define L_LAYERS 4
#define FULLM 0xffffffffu

// ---------------- device scratch ----------------
__device__ __align__(16) float g_h   [N_NODES * HID];
__device__ __align__(16) float g_hn  [N_NODES * HID];
__device__ __align__(16) float g_xlxr[N_NODES * 2 * HID];   // stride 192: [0:96)=xl, [96:192)=xr
__device__ __align__(16) int   g_cnt   [N_NODES];
__device__ __align__(16) int   g_rowptr[N_NODES + 1];
__device__ __align__(16) int   g_cursor[N_NODES];
__device__ __align__(16) int2  g_edge  [E_EDGES];   // (src, ew bits), sorted by dst
__device__ int g_is64;

// ---------------- edge_index dtype sniff ----------------
__global__ void detect_kernel(const int* ei32) {
    bool is64 = true;
    #pragma unroll
    for (int i = 0; i < 8; i++) if (ei32[2 * i + 1] != 0) is64 = false;
    g_is64 = is64 ? 1 : 0;
}

__device__ __forceinline__ void load_edge(const void* ei, int e, int& s, int& d) {
    if (g_is64) {
        const long long* p = (const long long*)ei;
        s = (int)p[e]; d = (int)p[E_EDGES + e];
    } else {
        const int* p = (const int*)ei;
        s = p[e]; d = p[E_EDGES + e];
    }
}

// ---------------- CSR build ----------------
__global__ void __launch_bounds__(256) hist_kernel(const void* ei) {
    int base = (blockIdx.x * blockDim.x + threadIdx.x) * 2;
    #pragma unroll
    for (int i = 0; i < 2; i++) {
        int e = base + i;
        if (e < E_EDGES) {
            int s, d; load_edge(ei, e, s, d);
            atomicAdd(&g_cnt[d], 1);
        }
    }
}

__global__ void __launch_bounds__(1024) scan_kernel() {
    __shared__ int ps[1024];
    int t = threadIdx.x;
    const int CH = (N_NODES + 1023) / 1024;
    int base = t * CH;
    int sum = 0;
    for (int i = 0; i < CH; i++) {
        int idx = base + i;
        if (idx < N_NODES) sum += g_cnt[idx];
    }
    ps[t] = sum;
    __syncthreads();
    for (int off = 1; off < 1024; off <<= 1) {
        int v = (t >= off) ? ps[t - off] : 0;
        __syncthreads();
        ps[t] += v;
        __syncthreads();
    }
    int run = ps[t] - sum;
    for (int i = 0; i < CH; i++) {
        int idx = base + i;
        if (idx < N_NODES) {
            g_rowptr[idx] = run;
            g_cursor[idx] = run;
            run += g_cnt[idx];
        }
    }
    if (t == 0) g_rowptr[N_NODES] = E_EDGES;
}

__global__ void __launch_bounds__(256) scatter_kernel(const void* ei, const float* __restrict__ ew) {
    int base = (blockIdx.x * blockDim.x + threadIdx.x) * 2;
    #pragma unroll
    for (int i = 0; i < 2; i++) {
        int e = base + i;
        if (e < E_EDGES) {
            int s, d; load_edge(ei, e, s, d);
            int p = atomicAdd(&g_cursor[d], 1);
            g_edge[p] = make_int2(s, __float_as_int(ew[e]));
        }
    }
}

// ---------------- packed-f32x2 helpers ----------------
__device__ __forceinline__ unsigned long long lds64(unsigned addr) {
    unsigned long long v;
    asm volatile("ld.shared.b64 %0, [%1];" : "=l"(v) : "r"(addr));
    return v;
}
__device__ __forceinline__ void ffma2(unsigned long long& d, unsigned long long a, unsigned long long b) {
    asm volatile("fma.rn.f32x2 %0, %1, %2, %0;" : "+l"(d) : "l"(a), "l"(b));
}

// ---------------- GEMM (R4-proven): C[nrows,CW] = A[nrows,K] @ [W1|W2] + [b1|b2] ----
// 256 threads; 64-row block tile; thread tile 8 rows x 3 col-pairs.
// A duplicated-float2 in smem (broadcast); W column-pairs via LDS.64.
template <int K, int CW, int CW1, int CLANES>
__global__ void __launch_bounds__(256) gemm2_kernel(
    const float* __restrict__ A,
    const float* __restrict__ W1, const float* __restrict__ W2,
    const float* __restrict__ b1, const float* __restrict__ b2,
    float* __restrict__ C, int nrows)
{
    constexpr int KCH = 32;
    constexpr int RPB = 64;
    constexpr int RG  = 256 / CLANES;
    constexpr int RPT = RPB / RG;
    constexpr int PS  = CW / 3;

    __shared__ float2 As2[RPB * KCH];
    __shared__ float  Ws[KCH * CW];

    const int tid = threadIdx.x;
    const int cx  = tid % CLANES;
    const int ry  = tid / CLANES;
    const int rowbase = blockIdx.x * RPB;

    unsigned aB = (unsigned)__cvta_generic_to_shared(As2);
    unsigned wB = (unsigned)__cvta_generic_to_shared(Ws);

    unsigned long long acc[RPT][3];
    #pragma unroll
    for (int j = 0; j < RPT; j++)
        #pragma unroll
        for (int c = 0; c < 3; c++) acc[j][c] = 0ULL;

    for (int kc = 0; kc < K; kc += KCH) {
        #pragma unroll
        for (int i = 0; i < 2; i++) {
            int f4  = tid + i * 256;
            int row = f4 >> 3;
            int kk  = (f4 & 7) * 4;
            float4 v = make_float4(0.f, 0.f, 0.f, 0.f);
            int grow = rowbase + row;
            if (grow < nrows) v = *(const float4*)(A + (size_t)grow * K + kc + kk);
            As2[row * KCH + kk + 0] = make_float2(v.x, v.x);
            As2[row * KCH + kk + 1] = make_float2(v.y, v.y);
            As2[row * KCH + kk + 2] = make_float2(v.z, v.z);
            As2[row * KCH + kk + 3] = make_float2(v.w, v.w);
        }
        #pragma unroll
        for (int i = 0; i < (KCH * CW) / 1024; i++) {
            int f = (tid + i * 256) * 4;
            int k = f / CW;
            int c = f % CW;
            float4 v;
            if (c < CW1) v = *(const float4*)(W1 + (size_t)(kc + k) * CW1 + c);
            else         v = *(const float4*)(W2 + (size_t)(kc + k) * (CW - CW1) + (c - CW1));
            *(float4*)(Ws + k * CW + c) = v;
        }
        __syncthreads();

        #pragma unroll 8
        for (int kk = 0; kk < KCH; kk++) {
            unsigned long long av[RPT];
            #pragma unroll
            for (int j = 0; j < RPT; j++)
                av[j] = lds64(aB + (unsigned)(((ry + RG * j) * KCH + kk) << 3));
            unsigned long long wv[3];
            #pragma unroll
            for (int c = 0; c < 3; c++)
                wv[c] = lds64(wB + (unsigned)((kk * CW + 2 * cx + PS * c) << 2));
            #pragma unroll
            for (int j = 0; j < RPT; j++)
                #pragma unroll
                for (int c = 0; c < 3; c++) ffma2(acc[j][c], av[j], wv[c]);
        }
        __syncthreads();
    }

    #pragma unroll
    for (int c = 0; c < 3; c++) {
        int col = 2 * cx + PS * c;
        float bv0, bv1;
        if (col < CW1) { bv0 = b1[col];       bv1 = b1[col + 1]; }
        else           { bv0 = b2[col - CW1]; bv1 = b2[col - CW1 + 1]; }
        #pragma unroll
        for (int j = 0; j < RPT; j++) {
            int grow = rowbase + ry + RG * j;
            if (grow < nrows) {
                float lo, hi;
                asm("mov.b64 {%0,%1}, %2;" : "=f"(lo), "=f"(hi) : "l"(acc[j][c]));
                *(float2*)(C + (size_t)grow * CW + col) = make_float2(lo + bv0, hi + bv1);
            }
        }
    }
}

// ---------------- warp reduce ----------------
__device__ __forceinline__ float wsum(float v) {
    #pragma unroll
    for (int o = 16; o > 0; o >>= 1) v += __shfl_xor_sync(FULLM, v, o);
    return v;
}
__device__ __forceinline__ float wmax(float v) {
    #pragma unroll
    for (int o = 16; o > 0; o >>= 1) v = fmaxf(v, __shfl_xor_sync(FULLM, v, o));
    return v;
}

// ---------------- initial LayerNorm + ReLU (h -> hn) ----------------
__global__ void __launch_bounds__(256) ln_init_kernel(
    const float* __restrict__ h,
    const float* __restrict__ g, const float* __restrict__ b,
    float* __restrict__ hn)
{
    int warp = threadIdx.x >> 5;
    int lane = threadIdx.x & 31;
    int n = blockIdx.x * 8 + warp;
    if (n >= N_NODES) return;
    size_t base = (size_t)n * HID;

    float v0 = h[base + lane], v1 = h[base + lane + 32], v2 = h[base + lane + 64];
    float mean = wsum(v0 + v1 + v2) * (1.0f / HID);
    float d0 = v0 - mean, d1 = v1 - mean, d2 = v2 - mean;
    float rstd = rsqrtf(wsum(fmaf(d0, d0, fmaf(d1, d1, d2 * d2))) * (1.0f / HID) + 1e-5f);
    hn[base + lane]      = fmaxf(fmaf(d0 * rstd, g[lane],      b[lane]),      0.f);
    hn[base + lane + 32] = fmaxf(fmaf(d1 * rstd, g[lane + 32], b[lane + 32]), 0.f);
    hn[base + lane + 64] = fmaxf(fmaf(d2 * rstd, g[lane + 64], b[lane + 64]), 0.f);
}

// ---------------- fused GAT layer (R5 pass-A subgroup reduction) ----------------
// Warp per node. Per 32-edge chunk:
//   pass A: 4 edges concurrently, 8 lanes each (3-shuffle sub-group reduce)
//   chunk-level online-softmax merge (one exp correction per chunk)
//   pass B: aggregation re-gathering the same rows (L1-hot, same launch)
__global__ void __launch_bounds__(256) gat_fused_kernel(
    const float* __restrict__ We,  const float* __restrict__ att,
    const float* __restrict__ bias,
    const float* __restrict__ lg,  const float* __restrict__ lb)
{
    __shared__ float sWe[HID], sAtt[HID], sBias[HID], sG[HID], sB[HID];
    int t = threadIdx.x;
    if (t < HID) {
        sWe[t] = We[t]; sAtt[t] = att[t]; sBias[t] = bias[t];
        sG[t] = lg[t];  sB[t]  = lb[t];
    }
    __syncthreads();

    int warp = t >> 5, lane = t & 31;
    int n = blockIdx.x * 8 + warp;
    if (n >= N_NODES) return;

    int l8  = lane & 7;
    int grp = lane >> 3;

    int r0 = g_rowptr[n], r1 = g_rowptr[n + 1];
    const float* xrp = g_xlxr + (size_t)n * 192 + 96;

    // float4 layout for pass A (lane covers dims l8*4 + c*32 + {0..3})
    float4 xr4[3], we4[3], at4[3];
    #pragma unroll
    for (int c = 0; c < 3; c++) {
        int k = c * 32 + l8 * 4;
        xr4[c] = *(const float4*)(xrp + k);
        we4[c] = *(const float4*)(sWe + k);
        at4[c] = *(const float4*)(sAtt + k);
    }

    float m = -INFINITY, ssum = 0.f;
    float a0 = 0.f, a1 = 0.f, a2 = 0.f;

    for (int c0 = r0; c0 < r1; c0 += 32) {
        int cnt = min(32, r1 - c0);
        int p = c0 + lane;
        int   si = 0;
        float wE = 0.f;
        if (lane < cnt) {
            int2 ed = g_edge[p];
            si = ed.x;
            wE = __int_as_float(ed.y);
        }

        // ---- pass A: 4 edges per iteration, 8-lane sub-group reduction
        float myal = -INFINITY;
        int iters = (cnt + 3) >> 2;
        for (int i = 0; i < iters; i++) {
            int eidx = 4 * i + grp;               // < 32 always
            int   se  = __shfl_sync(FULLM, si, eidx);
            float wEe = __shfl_sync(FULLM, wE, eidx);
            const float* xa = g_xlxr + (size_t)se * 192;

            float part = 0.f;
            #pragma unroll
            for (int c = 0; c < 3; c++) {
                float4 a = *(const float4*)(xa + c * 32 + l8 * 4);
                float4 r = xr4[c], w4 = we4[c], t4 = at4[c];
                float e0 = fmaf(wEe, w4.x, a.x + r.x); e0 = fmaxf(e0, 0.2f * e0);
                float e1 = fmaf(wEe, w4.y, a.y + r.y); e1 = fmaxf(e1, 0.2f * e1);
                float e2 = fmaf(wEe, w4.z, a.z + r.z); e2 = fmaxf(e2, 0.2f * e2);
                float e3 = fmaf(wEe, w4.w, a.w + r.w); e3 = fmaxf(e3, 0.2f * e3);
                part = fmaf(e0, t4.x, fmaf(e1, t4.y, fmaf(e2, t4.z, fmaf(e3, t4.w, part))));
            }
            part += __shfl_xor_sync(FULLM, part, 4);
            part += __shfl_xor_sync(FULLM, part, 2);
            part += __shfl_xor_sync(FULLM, part, 1);

            float bc = __shfl_sync(FULLM, part, (lane & 3) * 8);
            if ((lane >> 2) == i && lane < cnt) myal = bc;
        }

        // ---- chunk-level online softmax merge
        float cm = wmax(myal);
        float nm = fmaxf(m, cm);
        float corr = __expf(m - nm);
        ssum *= corr; a0 *= corr; a1 *= corr; a2 *= corr;
        float wexp = (lane < cnt) ? __expf(myal - nm) : 0.f;
        ssum += wsum(wexp);
        m = nm;

        // ---- pass B: aggregation (rows L1-hot from pass A)
        int jj = 0;
        for (; jj + 4 <= cnt; jj += 4) {
            float w0 = __shfl_sync(FULLM, wexp, jj + 0);
            float w1 = __shfl_sync(FULLM, wexp, jj + 1);
            float w2 = __shfl_sync(FULLM, wexp, jj + 2);
            float w3 = __shfl_sync(FULLM, wexp, jj + 3);
            const float* x0p = g_xlxr + (size_t)__shfl_sync(FULLM, si, jj + 0) * 192;
            const float* x1p = g_xlxr + (size_t)__shfl_sync(FULLM, si, jj + 1) * 192;
            const float* x2p = g_xlxr + (size_t)__shfl_sync(FULLM, si, jj + 2) * 192;
            const float* x3p = g_xlxr + (size_t)__shfl_sync(FULLM, si, jj + 3) * 192;
            float v00 = x0p[lane], v01 = x0p[lane + 32], v02 = x0p[lane + 64];
            float v10 = x1p[lane], v11 = x1p[lane + 32], v12 = x1p[lane + 64];
            float v20 = x2p[lane], v21 = x2p[lane + 32], v22 = x2p[lane + 64];
            float v30 = x3p[lane], v31 = x3p[lane + 32], v32 = x3p[lane + 64];
            a0 = fmaf(w0, v00, a0); a1 = fmaf(w0, v01, a1); a2 = fmaf(w0, v02, a2);
            a0 = fmaf(w1, v10, a0); a1 = fmaf(w1, v11, a1); a2 = fmaf(w1, v12, a2);
            a0 = fmaf(w2, v20, a0); a1 = fmaf(w2, v21, a1); a2 = fmaf(w2, v22, a2);
            a0 = fmaf(w3, v30, a0); a1 = fmaf(w3, v31, a1); a2 = fmaf(w3, v32, a2);
        }
        for (; jj < cnt; jj++) {
            float w = __shfl_sync(FULLM, wexp, jj);
            const float* xp = g_xlxr + (size_t)__shfl_sync(FULLM, si, jj) * 192;
            a0 = fmaf(w, xp[lane],      a0);
            a1 = fmaf(w, xp[lane + 32], a1);
            a2 = fmaf(w, xp[lane + 64], a2);
        }
    }

    float inv = 1.0f / (ssum + 1e-16f);
    a0 *= inv; a1 *= inv; a2 *= inv;

    // ---- residual + bias + LayerNorm + ReLU
    size_t base = (size_t)n * HID;
    float x0 = g_h[base + lane]      + a0 + sBias[lane];
    float x1 = g_h[base + lane + 32] + a1 + sBias[lane + 32];
    float x2 = g_h[base + lane + 64] + a2 + sBias[lane + 64];
    g_h[base + lane]      = x0;
    g_h[base + lane + 32] = x1;
    g_h[base + lane + 64] = x2;

    float mean = wsum(x0 + x1 + x2) * (1.0f / HID);
    float d0 = x0 - mean, d1 = x1 - mean, d2 = x2 - mean;
    float rstd = rsqrtf(wsum(fmaf(d0, d0, fmaf(d1, d1, d2 * d2))) * (1.0f / HID) + 1e-5f);
    g_hn[base + lane]      = fmaxf(fmaf(d0 * rstd, sG[lane],      sB[lane]),      0.f);
    g_hn[base + lane + 32] = fmaxf(fmaf(d1 * rstd, sG[lane + 32], sB[lane + 32]), 0.f);
    g_hn[base + lane + 64] = fmaxf(fmaf(d2 * rstd, sG[lane + 64], sB[lane + 64]), 0.f);
}

// ---------------- final FC ----------------
__global__ void __launch_bounds__(256) fc_kernel(
    const float* __restrict__ fcW, const float* __restrict__ fcb,
    float* __restrict__ out)
{
    int warp = threadIdx.x >> 5;
    int lane = threadIdx.x & 31;
    int n = blockIdx.x * 8 + warp;
    if (n >= N_NODES) return;
    size_t base = (size_t)n * HID;
    float acc = fmaf(g_hn[base + lane], fcW[lane],
                fmaf(g_hn[base + lane + 32], fcW[lane + 32],
                     g_hn[base + lane + 64] * fcW[lane + 64]));
    acc = wsum(acc);
    if (lane == 0) out[n] = acc + fcb[0];
}

// ---------------- launch ----------------
extern "C" void kernel_launch(void* const* d_in, const int* in_sizes, int n_in,
                              void* d_out, int out_size)
{
    const float* x    = (const float*)d_in[0];
    const void*  ei   = (const void*) d_in[1];
    const float* ew   = (const float*)d_in[2];
    const float* encW = (const float*)d_in[3];
    const float* encb = (const float*)d_in[4];
    const float* Wl   = (const float*)d_in[5];
    const float* bl   = (const float*)d_in[6];
    const float* Wr   = (const float*)d_in[7];
    const float* br   = (const float*)d_in[8];
    const float* We   = (const float*)d_in[9];
    const float* att  = (const float*)d_in[10];
    const float* bias = (const float*)d_in[11];
    const float* lng  = (const float*)d_in[12];
    const float* lnb  = (const float*)d_in[13];
    const float* lnfg = (const float*)d_in[14];
    const float* lnfb = (const float*)d_in[15];
    const float* fcW  = (const float*)d_in[16];
    const float* fcb  = (const float*)d_in[17];
    float*       out  = (float*)d_out;

    void *p_h, *p_hn, *p_cnt, *p_xlxr;
    cudaGetSymbolAddress(&p_h,    g_h);
    cudaGetSymbolAddress(&p_hn,   g_hn);
    cudaGetSymbolAddress(&p_cnt,  g_cnt);
    cudaGetSymbolAddress(&p_xlxr, g_xlxr);

    const int gemm_blocks  = (N_NODES + 63) / 64;       // 782
    const int node_blocks  = (N_NODES + 7) / 8;         // 6250
    const int edge2_blocks = (E_EDGES / 2 + 255) / 256; // 1563

    // CSR build (once per launch, shared by all 4 layers)
    detect_kernel<<<1, 1>>>((const int*)ei);
    cudaMemsetAsync(p_cnt, 0, N_NODES * sizeof(int));
    hist_kernel<<<edge2_blocks, 256>>>(ei);
    scan_kernel<<<1, 1024>>>();
    scatter_kernel<<<edge2_blocks, 256>>>(ei, ew);

    // encoder + first LN
    gemm2_kernel<F_IN, HID, HID, 16><<<gemm_blocks, 256>>>(
        x, encW, encW, encb, encb, (float*)p_h, N_NODES);
    ln_init_kernel<<<node_blocks, 256>>>((const float*)p_h, lng, lnb, (float*)p_hn);

    for (int i = 0; i < L_LAYERS; i++) {
        gemm2_kernel<HID, 2 * HID, HID, 32><<<gemm_blocks, 256>>>(
            (const float*)p_hn,
            Wl + (size_t)i * HID * HID, Wr + (size_t)i * HID * HID,
            bl + i * HID, br + i * HID, (float*)p_xlxr, N_NODES);

        const float* gnext = (i < L_LAYERS - 1) ? (lng + (i + 1) * HID) : lnfg;
        const float* bnext = (i < L_LAYERS - 1) ? (lnb + (i + 1) * HID) : lnfb;
        gat_fused_kernel<<<node_blocks, 256>>>(
            We + i * HID, att + i * HID, bias + i * HID, gnext, bnext);
    }

    fc_kernel<<<node_blocks, 256>>>(fcW, fcb, out);
}

// round 8
// speedup vs baseline: 1.0855x; 1.0855x over previous
#include <cuda_runtime.h>
#include <cstdint>
#include <math.h>

#define N_NODES 50000
#define E_EDGES 800000
#define F_IN    128
#define HID     96
#define L_LAYERS 4
#define FULLM 0xffffffffu

// ---------------- device scratch ----------------
__device__ __align__(16) float g_h   [N_NODES * HID];
__device__ __align__(16) float g_hn  [N_NODES * HID];
__device__ __align__(16) float g_xlxr[N_NODES * 2 * HID];   // stride 192: [0:96)=xl, [96:192)=xr
__device__ __align__(16) int   g_cnt   [N_NODES];
__device__ __align__(16) int   g_rowptr[N_NODES + 1];
__device__ __align__(16) int   g_cursor[N_NODES];
__device__ __align__(16) int2  g_edge  [E_EDGES];   // (src, ew bits), sorted by dst
__device__ int g_is64;

// ---------------- edge_index dtype sniff ----------------
__global__ void detect_kernel(const int* ei32) {
    bool is64 = true;
    #pragma unroll
    for (int i = 0; i < 8; i++) if (ei32[2 * i + 1] != 0) is64 = false;
    g_is64 = is64 ? 1 : 0;
}

__device__ __forceinline__ void load_edge(const void* ei, int e, int& s, int& d) {
    if (g_is64) {
        const long long* p = (const long long*)ei;
        s = (int)p[e]; d = (int)p[E_EDGES + e];
    } else {
        const int* p = (const int*)ei;
        s = p[e]; d = p[E_EDGES + e];
    }
}

// ---------------- CSR build ----------------
__global__ void __launch_bounds__(256) hist_kernel(const void* ei) {
    int base = (blockIdx.x * blockDim.x + threadIdx.x) * 2;
    #pragma unroll
    for (int i = 0; i < 2; i++) {
        int e = base + i;
        if (e < E_EDGES) {
            int s, d; load_edge(ei, e, s, d);
            atomicAdd(&g_cnt[d], 1);
        }
    }
}

__global__ void __launch_bounds__(1024) scan_kernel() {
    __shared__ int ps[1024];
    int t = threadIdx.x;
    const int CH = (N_NODES + 1023) / 1024;
    int base = t * CH;
    int sum = 0;
    for (int i = 0; i < CH; i++) {
        int idx = base + i;
        if (idx < N_NODES) sum += g_cnt[idx];
    }
    ps[t] = sum;
    __syncthreads();
    for (int off = 1; off < 1024; off <<= 1) {
        int v = (t >= off) ? ps[t - off] : 0;
        __syncthreads();
        ps[t] += v;
        __syncthreads();
    }
    int run = ps[t] - sum;
    for (int i = 0; i < CH; i++) {
        int idx = base + i;
        if (idx < N_NODES) {
            g_rowptr[idx] = run;
            g_cursor[idx] = run;
            run += g_cnt[idx];
        }
    }
    if (t == 0) g_rowptr[N_NODES] = E_EDGES;
}

__global__ void __launch_bounds__(256) scatter_kernel(const void* ei, const float* __restrict__ ew) {
    int base = (blockIdx.x * blockDim.x + threadIdx.x) * 2;
    #pragma unroll
    for (int i = 0; i < 2; i++) {
        int e = base + i;
        if (e < E_EDGES) {
            int s, d; load_edge(ei, e, s, d);
            int p = atomicAdd(&g_cursor[d], 1);
            g_edge[p] = make_int2(s, __float_as_int(ew[e]));
        }
    }
}

// ---------------- packed-f32x2 helpers ----------------
__device__ __forceinline__ unsigned long long lds64(unsigned addr) {
    unsigned long long v;
    asm volatile("ld.shared.b64 %0, [%1];" : "=l"(v) : "r"(addr));
    return v;
}
__device__ __forceinline__ void ffma2(unsigned long long& d, unsigned long long a, unsigned long long b) {
    asm volatile("fma.rn.f32x2 %0, %1, %2, %0;" : "+l"(d) : "l"(a), "l"(b));
}

// ---------------- GEMM (R4-proven): C[nrows,CW] = A[nrows,K] @ [W1|W2] + [b1|b2] ----
template <int K, int CW, int CW1, int CLANES>
__global__ void __launch_bounds__(256) gemm2_kernel(
    const float* __restrict__ A,
    const float* __restrict__ W1, const float* __restrict__ W2,
    const float* __restrict__ b1, const float* __restrict__ b2,
    float* __restrict__ C, int nrows)
{
    constexpr int KCH = 32;
    constexpr int RPB = 64;
    constexpr int RG  = 256 / CLANES;
    constexpr int RPT = RPB / RG;
    constexpr int PS  = CW / 3;

    __shared__ float2 As2[RPB * KCH];
    __shared__ float  Ws[KCH * CW];

    const int tid = threadIdx.x;
    const int cx  = tid % CLANES;
    const int ry  = tid / CLANES;
    const int rowbase = blockIdx.x * RPB;

    unsigned aB = (unsigned)__cvta_generic_to_shared(As2);
    unsigned wB = (unsigned)__cvta_generic_to_shared(Ws);

    unsigned long long acc[RPT][3];
    #pragma unroll
    for (int j = 0; j < RPT; j++)
        #pragma unroll
        for (int c = 0; c < 3; c++) acc[j][c] = 0ULL;

    for (int kc = 0; kc < K; kc += KCH) {
        #pragma unroll
        for (int i = 0; i < 2; i++) {
            int f4  = tid + i * 256;
            int row = f4 >> 3;
            int kk  = (f4 & 7) * 4;
            float4 v = make_float4(0.f, 0.f, 0.f, 0.f);
            int grow = rowbase + row;
            if (grow < nrows) v = *(const float4*)(A + (size_t)grow * K + kc + kk);
            As2[row * KCH + kk + 0] = make_float2(v.x, v.x);
            As2[row * KCH + kk + 1] = make_float2(v.y, v.y);
            As2[row * KCH + kk + 2] = make_float2(v.z, v.z);
            As2[row * KCH + kk + 3] = make_float2(v.w, v.w);
        }
        #pragma unroll
        for (int i = 0; i < (KCH * CW) / 1024; i++) {
            int f = (tid + i * 256) * 4;
            int k = f / CW;
            int c = f % CW;
            float4 v;
            if (c < CW1) v = *(const float4*)(W1 + (size_t)(kc + k) * CW1 + c);
            else         v = *(const float4*)(W2 + (size_t)(kc + k) * (CW - CW1) + (c - CW1));
            *(float4*)(Ws + k * CW + c) = v;
        }
        __syncthreads();

        #pragma unroll 8
        for (int kk = 0; kk < KCH; kk++) {
            unsigned long long av[RPT];
            #pragma unroll
            for (int j = 0; j < RPT; j++)
                av[j] = lds64(aB + (unsigned)(((ry + RG * j) * KCH + kk) << 3));
            unsigned long long wv[3];
            #pragma unroll
            for (int c = 0; c < 3; c++)
                wv[c] = lds64(wB + (unsigned)((kk * CW + 2 * cx + PS * c) << 2));
            #pragma unroll
            for (int j = 0; j < RPT; j++)
                #pragma unroll
                for (int c = 0; c < 3; c++) ffma2(acc[j][c], av[j], wv[c]);
        }
        __syncthreads();
    }

    #pragma unroll
    for (int c = 0; c < 3; c++) {
        int col = 2 * cx + PS * c;
        float bv0, bv1;
        if (col < CW1) { bv0 = b1[col];       bv1 = b1[col + 1]; }
        else           { bv0 = b2[col - CW1]; bv1 = b2[col - CW1 + 1]; }
        #pragma unroll
        for (int j = 0; j < RPT; j++) {
            int grow = rowbase + ry + RG * j;
            if (grow < nrows) {
                float lo, hi;
                asm("mov.b64 {%0,%1}, %2;" : "=f"(lo), "=f"(hi) : "l"(acc[j][c]));
                *(float2*)(C + (size_t)grow * CW + col) = make_float2(lo + bv0, hi + bv1);
            }
        }
    }
}

// ---------------- warp reduce ----------------
__device__ __forceinline__ float wsum(float v) {
    #pragma unroll
    for (int o = 16; o > 0; o >>= 1) v += __shfl_xor_sync(FULLM, v, o);
    return v;
}

// ---------------- initial LayerNorm + ReLU (h -> hn) ----------------
__global__ void __launch_bounds__(256) ln_init_kernel(
    const float* __restrict__ h,
    const float* __restrict__ g, const float* __restrict__ b,
    float* __restrict__ hn)
{
    int warp = threadIdx.x >> 5;
    int lane = threadIdx.x & 31;
    int n = blockIdx.x * 8 + warp;
    if (n >= N_NODES) return;
    size_t base = (size_t)n * HID;

    float v0 = h[base + lane], v1 = h[base + lane + 32], v2 = h[base + lane + 64];
    float mean = wsum(v0 + v1 + v2) * (1.0f / HID);
    float d0 = v0 - mean, d1 = v1 - mean, d2 = v2 - mean;
    float rstd = rsqrtf(wsum(fmaf(d0, d0, fmaf(d1, d1, d2 * d2))) * (1.0f / HID) + 1e-5f);
    hn[base + lane]      = fmaxf(fmaf(d0 * rstd, g[lane],      b[lane]),      0.f);
    hn[base + lane + 32] = fmaxf(fmaf(d1 * rstd, g[lane + 32], b[lane + 32]), 0.f);
    hn[base + lane + 64] = fmaxf(fmaf(d2 * rstd, g[lane + 64], b[lane + 64]), 0.f);
}

// ---------------- fused GAT layer: single-gather register retention ----------------
// Warp per node. 8-edge sub-chunks: gather 8 rows ONCE into regs (v[8][3]),
// interleaved 5-round butterfly leaves all 8 alphas in every lane ->
// softmax merge + aggregation are lane-uniform local ops (no extra shuffles).
__global__ void __launch_bounds__(256) gat_fused_kernel(
    const float* __restrict__ We,  const float* __restrict__ att,
    const float* __restrict__ bias,
    const float* __restrict__ lg,  const float* __restrict__ lb)
{
    __shared__ float sWe[HID], sAtt[HID], sBias[HID], sG[HID], sB[HID];
    int t = threadIdx.x;
    if (t < HID) {
        sWe[t] = We[t]; sAtt[t] = att[t]; sBias[t] = bias[t];
        sG[t] = lg[t];  sB[t]  = lb[t];
    }
    __syncthreads();

    int warp = t >> 5, lane = t & 31;
    int n = blockIdx.x * 8 + warp;
    if (n >= N_NODES) return;

    int r0 = g_rowptr[n], r1 = g_rowptr[n + 1];
    const float* xrp = g_xlxr + (size_t)n * 192 + 96;
    float xr0 = xrp[lane], xr1 = xrp[lane + 32], xr2 = xrp[lane + 64];
    float we0 = sWe[lane],  we1 = sWe[lane + 32],  we2 = sWe[lane + 64];
    float at0 = sAtt[lane], at1 = sAtt[lane + 32], at2 = sAtt[lane + 64];

    float m = -INFINITY, ssum = 0.f;
    float a0 = 0.f, a1 = 0.f, a2 = 0.f;

    for (int c0 = r0; c0 < r1; c0 += 8) {
        int cnt = min(8, r1 - c0);   // warp-uniform

        // ---- gather 8 rows + compute alpha partials (rows retained in regs)
        float v0[8], v1[8], v2[8], ta[8];
        #pragma unroll
        for (int e = 0; e < 8; e++) {
            if (e < cnt) {
                int2 ed = __ldg(&g_edge[c0 + e]);            // warp-uniform load
                float wEe = __int_as_float(ed.y);
                const float* xa = g_xlxr + (size_t)ed.x * 192;
                float x0 = xa[lane], x1 = xa[lane + 32], x2 = xa[lane + 64];
                v0[e] = x0; v1[e] = x1; v2[e] = x2;
                float e0 = fmaf(wEe, we0, x0 + xr0); e0 = fmaxf(e0, 0.2f * e0);
                float e1 = fmaf(wEe, we1, x1 + xr1); e1 = fmaxf(e1, 0.2f * e1);
                float e2 = fmaf(wEe, we2, x2 + xr2); e2 = fmaxf(e2, 0.2f * e2);
                ta[e] = fmaf(e0, at0, fmaf(e1, at1, e2 * at2));
            } else {
                v0[e] = 0.f; v1[e] = 0.f; v2[e] = 0.f;
                ta[e] = -INFINITY;
            }
        }

        // ---- interleaved butterfly: all 8 alphas fully reduced in ALL lanes
        #pragma unroll
        for (int o = 16; o > 0; o >>= 1) {
            #pragma unroll
            for (int e = 0; e < 8; e++)
                ta[e] += __shfl_xor_sync(FULLM, ta[e], o);
        }

        // ---- lane-uniform softmax merge + aggregation (no shuffles)
        float cm = ta[0];
        #pragma unroll
        for (int e = 1; e < 8; e++) cm = fmaxf(cm, ta[e]);
        float nm = fmaxf(m, cm);
        float corr = __expf(m - nm);
        ssum *= corr; a0 *= corr; a1 *= corr; a2 *= corr;
        #pragma unroll
        for (int e = 0; e < 8; e++) {
            float w = __expf(ta[e] - nm);        // 0 for padded edges
            ssum += w;
            a0 = fmaf(w, v0[e], a0);
            a1 = fmaf(w, v1[e], a1);
            a2 = fmaf(w, v2[e], a2);
        }
        m = nm;
    }

    float inv = 1.0f / (ssum + 1e-16f);
    a0 *= inv; a1 *= inv; a2 *= inv;

    // ---- residual + bias + LayerNorm + ReLU
    size_t base = (size_t)n * HID;
    float x0 = g_h[base + lane]      + a0 + sBias[lane];
    float x1 = g_h[base + lane + 32] + a1 + sBias[lane + 32];
    float x2 = g_h[base + lane + 64] + a2 + sBias[lane + 64];
    g_h[base + lane]      = x0;
    g_h[base + lane + 32] = x1;
    g_h[base + lane + 64] = x2;

    float mean = wsum(x0 + x1 + x2) * (1.0f / HID);
    float d0 = x0 - mean, d1 = x1 - mean, d2 = x2 - mean;
    float rstd = rsqrtf(wsum(fmaf(d0, d0, fmaf(d1, d1, d2 * d2))) * (1.0f / HID) + 1e-5f);
    g_hn[base + lane]      = fmaxf(fmaf(d0 * rstd, sG[lane],      sB[lane]),      0.f);
    g_hn[base + lane + 32] = fmaxf(fmaf(d1 * rstd, sG[lane + 32], sB[lane + 32]), 0.f);
    g_hn[base + lane + 64] = fmaxf(fmaf(d2 * rstd, sG[lane + 64], sB[lane + 64]), 0.f);
}

// ---------------- final FC ----------------
__global__ void __launch_bounds__(256) fc_kernel(
    const float* __restrict__ fcW, const float* __restrict__ fcb,
    float* __restrict__ out)
{
    int warp = threadIdx.x >> 5;
    int lane = threadIdx.x & 31;
    int n = blockIdx.x * 8 + warp;
    if (n >= N_NODES) return;
    size_t base = (size_t)n * HID;
    float acc = fmaf(g_hn[base + lane], fcW[lane],
                fmaf(g_hn[base + lane + 32], fcW[lane + 32],
                     g_hn[base + lane + 64] * fcW[lane + 64]));
    acc = wsum(acc);
    if (lane == 0) out[n] = acc + fcb[0];
}

// ---------------- launch ----------------
extern "C" void kernel_launch(void* const* d_in, const int* in_sizes, int n_in,
                              void* d_out, int out_size)
{
    const float* x    = (const float*)d_in[0];
    const void*  ei   = (const void*) d_in[1];
    const float* ew   = (const float*)d_in[2];
    const float* encW = (const float*)d_in[3];
    const float* encb = (const float*)d_in[4];
    const float* Wl   = (const float*)d_in[5];
    const float* bl   = (const float*)d_in[6];
    const float* Wr   = (const float*)d_in[7];
    const float* br   = (const float*)d_in[8];
    const float* We   = (const float*)d_in[9];
    const float* att  = (const float*)d_in[10];
    const float* bias = (const float*)d_in[11];
    const float* lng  = (const float*)d_in[12];
    const float* lnb  = (const float*)d_in[13];
    const float* lnfg = (const float*)d_in[14];
    const float* lnfb = (const float*)d_in[15];
    const float* fcW  = (const float*)d_in[16];
    const float* fcb  = (const float*)d_in[17];
    float*       out  = (float*)d_out;

    void *p_h, *p_hn, *p_cnt, *p_xlxr;
    cudaGetSymbolAddress(&p_h,    g_h);
    cudaGetSymbolAddress(&p_hn,   g_hn);
    cudaGetSymbolAddress(&p_cnt,  g_cnt);
    cudaGetSymbolAddress(&p_xlxr, g_xlxr);

    const int gemm_blocks  = (N_NODES + 63) / 64;       // 782
    const int node_blocks  = (N_NODES + 7) / 8;         // 6250
    const int edge2_blocks = (E_EDGES / 2 + 255) / 256; // 1563

    // CSR build (once per launch, shared by all 4 layers)
    detect_kernel<<<1, 1>>>((const int*)ei);
    cudaMemsetAsync(p_cnt, 0, N_NODES * sizeof(int));
    hist_kernel<<<edge2_blocks, 256>>>(ei);
    scan_kernel<<<1, 1024>>>();
    scatter_kernel<<<edge2_blocks, 256>>>(ei, ew);

    // encoder + first LN
    gemm2_kernel<F_IN, HID, HID, 16><<<gemm_blocks, 256>>>(
        x, encW, encW, encb, encb, (float*)p_h, N_NODES);
    ln_init_kernel<<<node_blocks, 256>>>((const float*)p_h, lng, lnb, (float*)p_hn);

    for (int i = 0; i < L_LAYERS; i++) {
        gemm2_kernel<HID, 2 * HID, HID, 32><<<gemm_blocks, 256>>>(
            (const float*)p_hn,
            Wl + (size_t)i * HID * HID, Wr + (size_t)i * HID * HID,
            bl + i * HID, br + i * HID, (float*)p_xlxr, N_NODES);

        const float* gnext = (i < L_LAYERS - 1) ? (lng + (i + 1) * HID) : lnfg;
        const float* bnext = (i < L_LAYERS - 1) ? (lnb + (i + 1) * HID) : lnfb;
        gat_fused_kernel<<<node_blocks, 256>>>(
            We + i * HID, att + i * HID, bias + i * HID, gnext, bnext);
    }

    fc_kernel<<<node_blocks, 256>>>(fcW, fcb, out);
}

// round 9
// speedup vs baseline: 1.1734x; 1.0809x over previous
#include <cuda_runtime.h>
#include <cstdint>
#include <math.h>

#define N_NODES 50000
#define E_EDGES 800000
#define F_IN    128
#define HID     96
#define L_LAYERS 4
#define FULLM 0xffffffffu

// ---------------- device scratch ----------------
__device__ __align__(16) float g_h   [N_NODES * HID];
__device__ __align__(16) float g_hn  [N_NODES * HID];
__device__ __align__(16) float g_xlxr[N_NODES * 2 * HID];   // stride 192: [0:96)=xl, [96:192)=xr
__device__ __align__(16) int   g_cnt   [N_NODES];
__device__ __align__(16) int   g_rowptr[N_NODES + 1];
__device__ __align__(16) int   g_cursor[N_NODES];
__device__ __align__(16) int2  g_edge  [E_EDGES];   // (src, ew bits), sorted by dst
__device__ int g_is64;

// ---------------- edge_index dtype sniff ----------------
__global__ void detect_kernel(const int* ei32) {
    bool is64 = true;
    #pragma unroll
    for (int i = 0; i < 8; i++) if (ei32[2 * i + 1] != 0) is64 = false;
    g_is64 = is64 ? 1 : 0;
}

__device__ __forceinline__ void load_edge(const void* ei, int e, int& s, int& d) {
    if (g_is64) {
        const long long* p = (const long long*)ei;
        s = (int)p[e]; d = (int)p[E_EDGES + e];
    } else {
        const int* p = (const int*)ei;
        s = p[e]; d = p[E_EDGES + e];
    }
}

// ---------------- CSR build ----------------
__global__ void __launch_bounds__(256) hist_kernel(const void* ei) {
    int base = (blockIdx.x * blockDim.x + threadIdx.x) * 2;
    #pragma unroll
    for (int i = 0; i < 2; i++) {
        int e = base + i;
        if (e < E_EDGES) {
            int s, d; load_edge(ei, e, s, d);
            atomicAdd(&g_cnt[d], 1);
        }
    }
}

__global__ void __launch_bounds__(1024) scan_kernel() {
    __shared__ int ps[1024];
    int t = threadIdx.x;
    const int CH = (N_NODES + 1023) / 1024;
    int base = t * CH;
    int sum = 0;
    for (int i = 0; i < CH; i++) {
        int idx = base + i;
        if (idx < N_NODES) sum += g_cnt[idx];
    }
    ps[t] = sum;
    __syncthreads();
    for (int off = 1; off < 1024; off <<= 1) {
        int v = (t >= off) ? ps[t - off] : 0;
        __syncthreads();
        ps[t] += v;
        __syncthreads();
    }
    int run = ps[t] - sum;
    for (int i = 0; i < CH; i++) {
        int idx = base + i;
        if (idx < N_NODES) {
            g_rowptr[idx] = run;
            g_cursor[idx] = run;
            run += g_cnt[idx];
        }
    }
    if (t == 0) g_rowptr[N_NODES] = E_EDGES;
}

__global__ void __launch_bounds__(256) scatter_kernel(const void* ei, const float* __restrict__ ew) {
    int base = (blockIdx.x * blockDim.x + threadIdx.x) * 2;
    #pragma unroll
    for (int i = 0; i < 2; i++) {
        int e = base + i;
        if (e < E_EDGES) {
            int s, d; load_edge(ei, e, s, d);
            int p = atomicAdd(&g_cursor[d], 1);
            g_edge[p] = make_int2(s, __float_as_int(ew[e]));
        }
    }
}

// ---------------- packed-f32x2 helpers ----------------
__device__ __forceinline__ unsigned long long lds64(unsigned addr) {
    unsigned long long v;
    asm volatile("ld.shared.b64 %0, [%1];" : "=l"(v) : "r"(addr));
    return v;
}
__device__ __forceinline__ void ffma2(unsigned long long& d, unsigned long long a, unsigned long long b) {
    asm volatile("fma.rn.f32x2 %0, %1, %2, %0;" : "+l"(d) : "l"(a), "l"(b));
}

// ---------------- GEMM (R4-proven): C[nrows,CW] = A[nrows,K] @ [W1|W2] + [b1|b2] ----
template <int K, int CW, int CW1, int CLANES>
__global__ void __launch_bounds__(256) gemm2_kernel(
    const float* __restrict__ A,
    const float* __restrict__ W1, const float* __restrict__ W2,
    const float* __restrict__ b1, const float* __restrict__ b2,
    float* __restrict__ C, int nrows)
{
    constexpr int KCH = 32;
    constexpr int RPB = 64;
    constexpr int RG  = 256 / CLANES;
    constexpr int RPT = RPB / RG;
    constexpr int PS  = CW / 3;

    __shared__ float2 As2[RPB * KCH];
    __shared__ float  Ws[KCH * CW];

    const int tid = threadIdx.x;
    const int cx  = tid % CLANES;
    const int ry  = tid / CLANES;
    const int rowbase = blockIdx.x * RPB;

    unsigned aB = (unsigned)__cvta_generic_to_shared(As2);
    unsigned wB = (unsigned)__cvta_generic_to_shared(Ws);

    unsigned long long acc[RPT][3];
    #pragma unroll
    for (int j = 0; j < RPT; j++)
        #pragma unroll
        for (int c = 0; c < 3; c++) acc[j][c] = 0ULL;

    for (int kc = 0; kc < K; kc += KCH) {
        #pragma unroll
        for (int i = 0; i < 2; i++) {
            int f4  = tid + i * 256;
            int row = f4 >> 3;
            int kk  = (f4 & 7) * 4;
            float4 v = make_float4(0.f, 0.f, 0.f, 0.f);
            int grow = rowbase + row;
            if (grow < nrows) v = *(const float4*)(A + (size_t)grow * K + kc + kk);
            As2[row * KCH + kk + 0] = make_float2(v.x, v.x);
            As2[row * KCH + kk + 1] = make_float2(v.y, v.y);
            As2[row * KCH + kk + 2] = make_float2(v.z, v.z);
            As2[row * KCH + kk + 3] = make_float2(v.w, v.w);
        }
        #pragma unroll
        for (int i = 0; i < (KCH * CW) / 1024; i++) {
            int f = (tid + i * 256) * 4;
            int k = f / CW;
            int c = f % CW;
            float4 v;
            if (c < CW1) v = *(const float4*)(W1 + (size_t)(kc + k) * CW1 + c);
            else         v = *(const float4*)(W2 + (size_t)(kc + k) * (CW - CW1) + (c - CW1));
            *(float4*)(Ws + k * CW + c) = v;
        }
        __syncthreads();

        #pragma unroll 8
        for (int kk = 0; kk < KCH; kk++) {
            unsigned long long av[RPT];
            #pragma unroll
            for (int j = 0; j < RPT; j++)
                av[j] = lds64(aB + (unsigned)(((ry + RG * j) * KCH + kk) << 3));
            unsigned long long wv[3];
            #pragma unroll
            for (int c = 0; c < 3; c++)
                wv[c] = lds64(wB + (unsigned)((kk * CW + 2 * cx + PS * c) << 2));
            #pragma unroll
            for (int j = 0; j < RPT; j++)
                #pragma unroll
                for (int c = 0; c < 3; c++) ffma2(acc[j][c], av[j], wv[c]);
        }
        __syncthreads();
    }

    #pragma unroll
    for (int c = 0; c < 3; c++) {
        int col = 2 * cx + PS * c;
        float bv0, bv1;
        if (col < CW1) { bv0 = b1[col];       bv1 = b1[col + 1]; }
        else           { bv0 = b2[col - CW1]; bv1 = b2[col - CW1 + 1]; }
        #pragma unroll
        for (int j = 0; j < RPT; j++) {
            int grow = rowbase + ry + RG * j;
            if (grow < nrows) {
                float lo, hi;
                asm("mov.b64 {%0,%1}, %2;" : "=f"(lo), "=f"(hi) : "l"(acc[j][c]));
                *(float2*)(C + (size_t)grow * CW + col) = make_float2(lo + bv0, hi + bv1);
            }
        }
    }
}

// ---------------- warp reduce ----------------
__device__ __forceinline__ float wsum(float v) {
    #pragma unroll
    for (int o = 16; o > 0; o >>= 1) v += __shfl_xor_sync(FULLM, v, o);
    return v;
}
__device__ __forceinline__ float wmax(float v) {
    #pragma unroll
    for (int o = 16; o > 0; o >>= 1) v = fmaxf(v, __shfl_xor_sync(FULLM, v, o));
    return v;
}

// ---------------- initial LayerNorm + ReLU (h -> hn) ----------------
__global__ void __launch_bounds__(256) ln_init_kernel(
    const float* __restrict__ h,
    const float* __restrict__ g, const float* __restrict__ b,
    float* __restrict__ hn)
{
    int warp = threadIdx.x >> 5;
    int lane = threadIdx.x & 31;
    int n = blockIdx.x * 8 + warp;
    if (n >= N_NODES) return;
    size_t base = (size_t)n * HID;

    float v0 = h[base + lane], v1 = h[base + lane + 32], v2 = h[base + lane + 64];
    float mean = wsum(v0 + v1 + v2) * (1.0f / HID);
    float d0 = v0 - mean, d1 = v1 - mean, d2 = v2 - mean;
    float rstd = rsqrtf(wsum(fmaf(d0, d0, fmaf(d1, d1, d2 * d2))) * (1.0f / HID) + 1e-5f);
    hn[base + lane]      = fmaxf(fmaf(d0 * rstd, g[lane],      b[lane]),      0.f);
    hn[base + lane + 32] = fmaxf(fmaf(d1 * rstd, g[lane + 32], b[lane + 32]), 0.f);
    hn[base + lane + 64] = fmaxf(fmaf(d2 * rstd, g[lane + 64], b[lane + 64]), 0.f);
}

// ---------------- fused GAT layer (R4-proven, unchanged) ----------------
__global__ void __launch_bounds__(256) gat_fused_kernel(
    const float* __restrict__ We,  const float* __restrict__ att,
    const float* __restrict__ bias,
    const float* __restrict__ lg,  const float* __restrict__ lb)
{
    __shared__ float sWe[HID], sAtt[HID], sBias[HID], sG[HID], sB[HID];
    int t = threadIdx.x;
    if (t < HID) {
        sWe[t] = We[t]; sAtt[t] = att[t]; sBias[t] = bias[t];
        sG[t] = lg[t];  sB[t]  = lb[t];
    }
    __syncthreads();

    int warp = t >> 5, lane = t & 31;
    int n = blockIdx.x * 8 + warp;
    if (n >= N_NODES) return;

    int r0 = g_rowptr[n], r1 = g_rowptr[n + 1];
    const float* xrp = g_xlxr + (size_t)n * 192 + 96;
    float xr0 = xrp[lane], xr1 = xrp[lane + 32], xr2 = xrp[lane + 64];
    float we0 = sWe[lane],  we1 = sWe[lane + 32],  we2 = sWe[lane + 64];
    float at0 = sAtt[lane], at1 = sAtt[lane + 32], at2 = sAtt[lane + 64];

    float m = -INFINITY, ssum = 0.f;
    float a0 = 0.f, a1 = 0.f, a2 = 0.f;

    for (int c0 = r0; c0 < r1; c0 += 32) {
        int cnt = min(32, r1 - c0);
        int p = c0 + lane;
        int   si = 0;
        float wE = 0.f;
        if (lane < cnt) {
            int2 ed = g_edge[p];
            si = ed.x;
            wE = __int_as_float(ed.y);
        }

        // ---- pass A: alpha per edge (coalesced row loads, independent reduces)
        float myal = -INFINITY;
        int j = 0;
        for (; j + 2 <= cnt; j += 2) {
            int   sa = __shfl_sync(FULLM, si, j);
            int   sb = __shfl_sync(FULLM, si, j + 1);
            float wa = __shfl_sync(FULLM, wE, j);
            float wb = __shfl_sync(FULLM, wE, j + 1);
            const float* xa = g_xlxr + (size_t)sa * 192;
            const float* xb = g_xlxr + (size_t)sb * 192;
            float xa0 = xa[lane], xa1 = xa[lane + 32], xa2 = xa[lane + 64];
            float xb0 = xb[lane], xb1 = xb[lane + 32], xb2 = xb[lane + 64];

            float e0 = xa0 + xr0 + wa * we0; e0 = e0 > 0.f ? e0 : 0.2f * e0;
            float e1 = xa1 + xr1 + wa * we1; e1 = e1 > 0.f ? e1 : 0.2f * e1;
            float e2 = xa2 + xr2 + wa * we2; e2 = e2 > 0.f ? e2 : 0.2f * e2;
            float ta = fmaf(e0, at0, fmaf(e1, at1, e2 * at2));

            float f0 = xb0 + xr0 + wb * we0; f0 = f0 > 0.f ? f0 : 0.2f * f0;
            float f1 = xb1 + xr1 + wb * we1; f1 = f1 > 0.f ? f1 : 0.2f * f1;
            float f2 = xb2 + xr2 + wb * we2; f2 = f2 > 0.f ? f2 : 0.2f * f2;
            float tb = fmaf(f0, at0, fmaf(f1, at1, f2 * at2));

            #pragma unroll
            for (int o = 16; o > 0; o >>= 1) {
                ta += __shfl_xor_sync(FULLM, ta, o);
                tb += __shfl_xor_sync(FULLM, tb, o);
            }
            myal = (lane == j)     ? ta : myal;
            myal = (lane == j + 1) ? tb : myal;
        }
        if (j < cnt) {
            int   sa = __shfl_sync(FULLM, si, j);
            float wa = __shfl_sync(FULLM, wE, j);
            const float* xa = g_xlxr + (size_t)sa * 192;
            float xa0 = xa[lane], xa1 = xa[lane + 32], xa2 = xa[lane + 64];
            float e0 = xa0 + xr0 + wa * we0; e0 = e0 > 0.f ? e0 : 0.2f * e0;
            float e1 = xa1 + xr1 + wa * we1; e1 = e1 > 0.f ? e1 : 0.2f * e1;
            float e2 = xa2 + xr2 + wa * we2; e2 = e2 > 0.f ? e2 : 0.2f * e2;
            float ta = fmaf(e0, at0, fmaf(e1, at1, e2 * at2));
            #pragma unroll
            for (int o = 16; o > 0; o >>= 1) ta += __shfl_xor_sync(FULLM, ta, o);
            myal = (lane == j) ? ta : myal;
        }

        // ---- chunk-level online softmax merge
        float cm = wmax(myal);
        float nm = fmaxf(m, cm);
        float corr = __expf(m - nm);
        ssum *= corr; a0 *= corr; a1 *= corr; a2 *= corr;
        float wexp = (lane < cnt) ? __expf(myal - nm) : 0.f;
        ssum += wsum(wexp);
        m = nm;

        // ---- pass B: aggregation (rows L1-hot from pass A)
        int jj = 0;
        for (; jj + 4 <= cnt; jj += 4) {
            float w0 = __shfl_sync(FULLM, wexp, jj + 0);
            float w1 = __shfl_sync(FULLM, wexp, jj + 1);
            float w2 = __shfl_sync(FULLM, wexp, jj + 2);
            float w3 = __shfl_sync(FULLM, wexp, jj + 3);
            const float* x0p = g_xlxr + (size_t)__shfl_sync(FULLM, si, jj + 0) * 192;
            const float* x1p = g_xlxr + (size_t)__shfl_sync(FULLM, si, jj + 1) * 192;
            const float* x2p = g_xlxr + (size_t)__shfl_sync(FULLM, si, jj + 2) * 192;
            const float* x3p = g_xlxr + (size_t)__shfl_sync(FULLM, si, jj + 3) * 192;
            float v00 = x0p[lane], v01 = x0p[lane + 32], v02 = x0p[lane + 64];
            float v10 = x1p[lane], v11 = x1p[lane + 32], v12 = x1p[lane + 64];
            float v20 = x2p[lane], v21 = x2p[lane + 32], v22 = x2p[lane + 64];
            float v30 = x3p[lane], v31 = x3p[lane + 32], v32 = x3p[lane + 64];
            a0 = fmaf(w0, v00, a0); a1 = fmaf(w0, v01, a1); a2 = fmaf(w0, v02, a2);
            a0 = fmaf(w1, v10, a0); a1 = fmaf(w1, v11, a1); a2 = fmaf(w1, v12, a2);
            a0 = fmaf(w2, v20, a0); a1 = fmaf(w2, v21, a1); a2 = fmaf(w2, v22, a2);
            a0 = fmaf(w3, v30, a0); a1 = fmaf(w3, v31, a1); a2 = fmaf(w3, v32, a2);
        }
        for (; jj < cnt; jj++) {
            float w = __shfl_sync(FULLM, wexp, jj);
            const float* xp = g_xlxr + (size_t)__shfl_sync(FULLM, si, jj) * 192;
            a0 = fmaf(w, xp[lane],      a0);
            a1 = fmaf(w, xp[lane + 32], a1);
            a2 = fmaf(w, xp[lane + 64], a2);
        }
    }

    float inv = 1.0f / (ssum + 1e-16f);
    a0 *= inv; a1 *= inv; a2 *= inv;

    // ---- residual + bias + LayerNorm + ReLU
    size_t base = (size_t)n * HID;
    float x0 = g_h[base + lane]      + a0 + sBias[lane];
    float x1 = g_h[base + lane + 32] + a1 + sBias[lane + 32];
    float x2 = g_h[base + lane + 64] + a2 + sBias[lane + 64];
    g_h[base + lane]      = x0;
    g_h[base + lane + 32] = x1;
    g_h[base + lane + 64] = x2;

    float mean = wsum(x0 + x1 + x2) * (1.0f / HID);
    float d0 = x0 - mean, d1 = x1 - mean, d2 = x2 - mean;
    float rstd = rsqrtf(wsum(fmaf(d0, d0, fmaf(d1, d1, d2 * d2))) * (1.0f / HID) + 1e-5f);
    g_hn[base + lane]      = fmaxf(fmaf(d0 * rstd, sG[lane],      sB[lane]),      0.f);
    g_hn[base + lane + 32] = fmaxf(fmaf(d1 * rstd, sG[lane + 32], sB[lane + 32]), 0.f);
    g_hn[base + lane + 64] = fmaxf(fmaf(d2 * rstd, sG[lane + 64], sB[lane + 64]), 0.f);
}

// ---------------- final FC ----------------
__global__ void __launch_bounds__(256) fc_kernel(
    const float* __restrict__ fcW, const float* __restrict__ fcb,
    float* __restrict__ out)
{
    int warp = threadIdx.x >> 5;
    int lane = threadIdx.x & 31;
    int n = blockIdx.x * 8 + warp;
    if (n >= N_NODES) return;
    size_t base = (size_t)n * HID;
    float acc = fmaf(g_hn[base + lane], fcW[lane],
                fmaf(g_hn[base + lane + 32], fcW[lane + 32],
                     g_hn[base + lane + 64] * fcW[lane + 64]));
    acc = wsum(acc);
    if (lane == 0) out[n] = acc + fcb[0];
}

// ---------------- launch ----------------
extern "C" void kernel_launch(void* const* d_in, const int* in_sizes, int n_in,
                              void* d_out, int out_size)
{
    const float* x    = (const float*)d_in[0];
    const void*  ei   = (const void*) d_in[1];
    const float* ew   = (const float*)d_in[2];
    const float* encW = (const float*)d_in[3];
    const float* encb = (const float*)d_in[4];
    const float* Wl   = (const float*)d_in[5];
    const float* bl   = (const float*)d_in[6];
    const float* Wr   = (const float*)d_in[7];
    const float* br   = (const float*)d_in[8];
    const float* We   = (const float*)d_in[9];
    const float* att  = (const float*)d_in[10];
    const float* bias = (const float*)d_in[11];
    const float* lng  = (const float*)d_in[12];
    const float* lnb  = (const float*)d_in[13];
    const float* lnfg = (const float*)d_in[14];
    const float* lnfb = (const float*)d_in[15];
    const float* fcW  = (const float*)d_in[16];
    const float* fcb  = (const float*)d_in[17];
    float*       out  = (float*)d_out;

    void *p_h, *p_hn, *p_cnt, *p_xlxr;
    cudaGetSymbolAddress(&p_h,    g_h);
    cudaGetSymbolAddress(&p_hn,   g_hn);
    cudaGetSymbolAddress(&p_cnt,  g_cnt);
    cudaGetSymbolAddress(&p_xlxr, g_xlxr);

    const int gemm_blocks  = (N_NODES + 63) / 64;       // 782
    const int node_blocks  = (N_NODES + 7) / 8;         // 6250
    const int edge2_blocks = (E_EDGES / 2 + 255) / 256; // 1563

    // ---- fork: CSR build on side stream, encoder on main (capture) stream ----
    cudaStream_t s2;
    cudaStreamCreateWithFlags(&s2, cudaStreamNonBlocking);
    cudaEvent_t evFork, evJoin;
    cudaEventCreateWithFlags(&evFork, cudaEventDisableTiming);
    cudaEventCreateWithFlags(&evJoin, cudaEventDisableTiming);

    cudaEventRecord(evFork, 0);
    cudaStreamWaitEvent(s2, evFork, 0);

    // side stream: CSR build (independent of encoder path)
    detect_kernel<<<1, 1, 0, s2>>>((const int*)ei);
    cudaMemsetAsync(p_cnt, 0, N_NODES * sizeof(int), s2);
    hist_kernel<<<edge2_blocks, 256, 0, s2>>>(ei);
    scan_kernel<<<1, 1024, 0, s2>>>();
    scatter_kernel<<<edge2_blocks, 256, 0, s2>>>(ei, ew);
    cudaEventRecord(evJoin, s2);

    // main stream: encoder GEMM + first LN (independent of CSR)
    gemm2_kernel<F_IN, HID, HID, 16><<<gemm_blocks, 256>>>(
        x, encW, encW, encb, encb, (float*)p_h, N_NODES);
    ln_init_kernel<<<node_blocks, 256>>>((const float*)p_h, lng, lnb, (float*)p_hn);

    // join: layer loop needs both CSR and hn
    cudaStreamWaitEvent(0, evJoin, 0);

    for (int i = 0; i < L_LAYERS; i++) {
        gemm2_kernel<HID, 2 * HID, HID, 32><<<gemm_blocks, 256>>>(
            (const float*)p_hn,
            Wl + (size_t)i * HID * HID, Wr + (size_t)i * HID * HID,
            bl + i * HID, br + i * HID, (float*)p_xlxr, N_NODES);

        const float* gnext = (i < L_LAYERS - 1) ? (lng + (i + 1) * HID) : lnfg;
        const float* bnext = (i < L_LAYERS - 1) ? (lnb + (i + 1) * HID) : lnfb;
        gat_fused_kernel<<<node_blocks, 256>>>(
            We + i * HID, att + i * HID, bias + i * HID, gnext, bnext);
    }

    fc_kernel<<<node_blocks, 256>>>(fcW, fcb, out);

    cudaEventDestroy(evFork);
    cudaEventDestroy(evJoin);
    cudaStreamDestroy(s2);
}

// round 10
// speedup vs baseline: 1.2181x; 1.0381x over previous
#include <cuda_runtime.h>
#include <cstdint>
#include <math.h>

#define N_NODES 50000
#define NHALF   25024          // multiple of 64 and 8
#define E_EDGES 800000
#define F_IN    128
#define HID     96
#define L_LAYERS 4
#define FULLM 0xffffffffu

// ---------------- device scratch ----------------
__device__ __align__(16) float g_h    [N_NODES * HID];
__device__ __align__(16) float g_hn   [N_NODES * HID];
__device__ __align__(16) float g_xlxr0[N_NODES * 2 * HID];  // ping
__device__ __align__(16) float g_xlxr1[N_NODES * 2 * HID];  // pong
__device__ __align__(16) int   g_cnt   [N_NODES];
__device__ __align__(16) int   g_rowptr[N_NODES + 1];
__device__ __align__(16) int   g_cursor[N_NODES];
__device__ __align__(16) int2  g_edge  [E_EDGES];   // (src, ew bits), sorted by dst
__device__ int g_is64;

// ---------------- edge_index dtype sniff ----------------
__global__ void detect_kernel(const int* ei32) {
    bool is64 = true;
    #pragma unroll
    for (int i = 0; i < 8; i++) if (ei32[2 * i + 1] != 0) is64 = false;
    g_is64 = is64 ? 1 : 0;
}

__device__ __forceinline__ void load_edge(const void* ei, int e, int& s, int& d) {
    if (g_is64) {
        const long long* p = (const long long*)ei;
        s = (int)p[e]; d = (int)p[E_EDGES + e];
    } else {
        const int* p = (const int*)ei;
        s = p[e]; d = p[E_EDGES + e];
    }
}

// ---------------- CSR build ----------------
__global__ void __launch_bounds__(256) hist_kernel(const void* ei) {
    int base = (blockIdx.x * blockDim.x + threadIdx.x) * 2;
    #pragma unroll
    for (int i = 0; i < 2; i++) {
        int e = base + i;
        if (e < E_EDGES) {
            int s, d; load_edge(ei, e, s, d);
            atomicAdd(&g_cnt[d], 1);
        }
    }
}

__global__ void __launch_bounds__(1024) scan_kernel() {
    __shared__ int ps[1024];
    int t = threadIdx.x;
    const int CH = (N_NODES + 1023) / 1024;
    int base = t * CH;
    int sum = 0;
    for (int i = 0; i < CH; i++) {
        int idx = base + i;
        if (idx < N_NODES) sum += g_cnt[idx];
    }
    ps[t] = sum;
    __syncthreads();
    for (int off = 1; off < 1024; off <<= 1) {
        int v = (t >= off) ? ps[t - off] : 0;
        __syncthreads();
        ps[t] += v;
        __syncthreads();
    }
    int run = ps[t] - sum;
    for (int i = 0; i < CH; i++) {
        int idx = base + i;
        if (idx < N_NODES) {
            g_rowptr[idx] = run;
            g_cursor[idx] = run;
            run += g_cnt[idx];
        }
    }
    if (t == 0) g_rowptr[N_NODES] = E_EDGES;
}

__global__ void __launch_bounds__(256) scatter_kernel(const void* ei, const float* __restrict__ ew) {
    int base = (blockIdx.x * blockDim.x + threadIdx.x) * 2;
    #pragma unroll
    for (int i = 0; i < 2; i++) {
        int e = base + i;
        if (e < E_EDGES) {
            int s, d; load_edge(ei, e, s, d);
            int p = atomicAdd(&g_cursor[d], 1);
            g_edge[p] = make_int2(s, __float_as_int(ew[e]));
        }
    }
}

// ---------------- packed-f32x2 helpers ----------------
__device__ __forceinline__ unsigned long long lds64(unsigned addr) {
    unsigned long long v;
    asm volatile("ld.shared.b64 %0, [%1];" : "=l"(v) : "r"(addr));
    return v;
}
__device__ __forceinline__ void ffma2(unsigned long long& d, unsigned long long a, unsigned long long b) {
    asm volatile("fma.rn.f32x2 %0, %1, %2, %0;" : "+l"(d) : "l"(a), "l"(b));
}

// ---------------- GEMM (R4-proven, range-parameterized) ----------------
template <int K, int CW, int CW1, int CLANES>
__global__ void __launch_bounds__(256) gemm2_kernel(
    const float* __restrict__ A,
    const float* __restrict__ W1, const float* __restrict__ W2,
    const float* __restrict__ b1, const float* __restrict__ b2,
    float* __restrict__ C, int rbeg, int rend)
{
    constexpr int KCH = 32;
    constexpr int RPB = 64;
    constexpr int RG  = 256 / CLANES;
    constexpr int RPT = RPB / RG;
    constexpr int PS  = CW / 3;

    __shared__ float2 As2[RPB * KCH];
    __shared__ float  Ws[KCH * CW];

    const int tid = threadIdx.x;
    const int cx  = tid % CLANES;
    const int ry  = tid / CLANES;
    const int rowbase = rbeg + blockIdx.x * RPB;

    unsigned aB = (unsigned)__cvta_generic_to_shared(As2);
    unsigned wB = (unsigned)__cvta_generic_to_shared(Ws);

    unsigned long long acc[RPT][3];
    #pragma unroll
    for (int j = 0; j < RPT; j++)
        #pragma unroll
        for (int c = 0; c < 3; c++) acc[j][c] = 0ULL;

    for (int kc = 0; kc < K; kc += KCH) {
        #pragma unroll
        for (int i = 0; i < 2; i++) {
            int f4  = tid + i * 256;
            int row = f4 >> 3;
            int kk  = (f4 & 7) * 4;
            float4 v = make_float4(0.f, 0.f, 0.f, 0.f);
            int grow = rowbase + row;
            if (grow < rend) v = *(const float4*)(A + (size_t)grow * K + kc + kk);
            As2[row * KCH + kk + 0] = make_float2(v.x, v.x);
            As2[row * KCH + kk + 1] = make_float2(v.y, v.y);
            As2[row * KCH + kk + 2] = make_float2(v.z, v.z);
            As2[row * KCH + kk + 3] = make_float2(v.w, v.w);
        }
        #pragma unroll
        for (int i = 0; i < (KCH * CW) / 1024; i++) {
            int f = (tid + i * 256) * 4;
            int k = f / CW;
            int c = f % CW;
            float4 v;
            if (c < CW1) v = *(const float4*)(W1 + (size_t)(kc + k) * CW1 + c);
            else         v = *(const float4*)(W2 + (size_t)(kc + k) * (CW - CW1) + (c - CW1));
            *(float4*)(Ws + k * CW + c) = v;
        }
        __syncthreads();

        #pragma unroll 8
        for (int kk = 0; kk < KCH; kk++) {
            unsigned long long av[RPT];
            #pragma unroll
            for (int j = 0; j < RPT; j++)
                av[j] = lds64(aB + (unsigned)(((ry + RG * j) * KCH + kk) << 3));
            unsigned long long wv[3];
            #pragma unroll
            for (int c = 0; c < 3; c++)
                wv[c] = lds64(wB + (unsigned)((kk * CW + 2 * cx + PS * c) << 2));
            #pragma unroll
            for (int j = 0; j < RPT; j++)
                #pragma unroll
                for (int c = 0; c < 3; c++) ffma2(acc[j][c], av[j], wv[c]);
        }
        __syncthreads();
    }

    #pragma unroll
    for (int c = 0; c < 3; c++) {
        int col = 2 * cx + PS * c;
        float bv0, bv1;
        if (col < CW1) { bv0 = b1[col];       bv1 = b1[col + 1]; }
        else           { bv0 = b2[col - CW1]; bv1 = b2[col - CW1 + 1]; }
        #pragma unroll
        for (int j = 0; j < RPT; j++) {
            int grow = rowbase + ry + RG * j;
            if (grow < rend) {
                float lo, hi;
                asm("mov.b64 {%0,%1}, %2;" : "=f"(lo), "=f"(hi) : "l"(acc[j][c]));
                *(float2*)(C + (size_t)grow * CW + col) = make_float2(lo + bv0, hi + bv1);
            }
        }
    }
}

// ---------------- warp reduce ----------------
__device__ __forceinline__ float wsum(float v) {
    #pragma unroll
    for (int o = 16; o > 0; o >>= 1) v += __shfl_xor_sync(FULLM, v, o);
    return v;
}
__device__ __forceinline__ float wmax(float v) {
    #pragma unroll
    for (int o = 16; o > 0; o >>= 1) v = fmaxf(v, __shfl_xor_sync(FULLM, v, o));
    return v;
}

// ---------------- initial LayerNorm + ReLU (h -> hn), range-parameterized ----------------
__global__ void __launch_bounds__(256) ln_init_kernel(
    const float* __restrict__ h,
    const float* __restrict__ g, const float* __restrict__ b,
    float* __restrict__ hn, int nbeg, int nend)
{
    int warp = threadIdx.x >> 5;
    int lane = threadIdx.x & 31;
    int n = nbeg + blockIdx.x * 8 + warp;
    if (n >= nend) return;
    size_t base = (size_t)n * HID;

    float v0 = h[base + lane], v1 = h[base + lane + 32], v2 = h[base + lane + 64];
    float mean = wsum(v0 + v1 + v2) * (1.0f / HID);
    float d0 = v0 - mean, d1 = v1 - mean, d2 = v2 - mean;
    float rstd = rsqrtf(wsum(fmaf(d0, d0, fmaf(d1, d1, d2 * d2))) * (1.0f / HID) + 1e-5f);
    hn[base + lane]      = fmaxf(fmaf(d0 * rstd, g[lane],      b[lane]),      0.f);
    hn[base + lane + 32] = fmaxf(fmaf(d1 * rstd, g[lane + 32], b[lane + 32]), 0.f);
    hn[base + lane + 64] = fmaxf(fmaf(d2 * rstd, g[lane + 64], b[lane + 64]), 0.f);
}

// ---------------- fused GAT layer (R4-proven body; xlxr pointer + range params) ----------
__global__ void __launch_bounds__(256) gat_fused_kernel(
    const float* __restrict__ xlxr,
    const float* __restrict__ We,  const float* __restrict__ att,
    const float* __restrict__ bias,
    const float* __restrict__ lg,  const float* __restrict__ lb,
    int nbeg, int nend)
{
    __shared__ float sWe[HID], sAtt[HID], sBias[HID], sG[HID], sB[HID];
    int t = threadIdx.x;
    if (t < HID) {
        sWe[t] = We[t]; sAtt[t] = att[t]; sBias[t] = bias[t];
        sG[t] = lg[t];  sB[t]  = lb[t];
    }
    __syncthreads();

    int warp = t >> 5, lane = t & 31;
    int n = nbeg + blockIdx.x * 8 + warp;
    if (n >= nend) return;

    int r0 = g_rowptr[n], r1 = g_rowptr[n + 1];
    const float* xrp = xlxr + (size_t)n * 192 + 96;
    float xr0 = xrp[lane], xr1 = xrp[lane + 32], xr2 = xrp[lane + 64];
    float we0 = sWe[lane],  we1 = sWe[lane + 32],  we2 = sWe[lane + 64];
    float at0 = sAtt[lane], at1 = sAtt[lane + 32], at2 = sAtt[lane + 64];

    float m = -INFINITY, ssum = 0.f;
    float a0 = 0.f, a1 = 0.f, a2 = 0.f;

    for (int c0 = r0; c0 < r1; c0 += 32) {
        int cnt = min(32, r1 - c0);
        int p = c0 + lane;
        int   si = 0;
        float wE = 0.f;
        if (lane < cnt) {
            int2 ed = g_edge[p];
            si = ed.x;
            wE = __int_as_float(ed.y);
        }

        // ---- pass A: alpha per edge (coalesced row loads, independent reduces)
        float myal = -INFINITY;
        int j = 0;
        for (; j + 2 <= cnt; j += 2) {
            int   sa = __shfl_sync(FULLM, si, j);
            int   sb = __shfl_sync(FULLM, si, j + 1);
            float wa = __shfl_sync(FULLM, wE, j);
            float wb = __shfl_sync(FULLM, wE, j + 1);
            const float* xa = xlxr + (size_t)sa * 192;
            const float* xb = xlxr + (size_t)sb * 192;
            float xa0 = xa[lane], xa1 = xa[lane + 32], xa2 = xa[lane + 64];
            float xb0 = xb[lane], xb1 = xb[lane + 32], xb2 = xb[lane + 64];

            float e0 = xa0 + xr0 + wa * we0; e0 = e0 > 0.f ? e0 : 0.2f * e0;
            float e1 = xa1 + xr1 + wa * we1; e1 = e1 > 0.f ? e1 : 0.2f * e1;
            float e2 = xa2 + xr2 + wa * we2; e2 = e2 > 0.f ? e2 : 0.2f * e2;
            float ta = fmaf(e0, at0, fmaf(e1, at1, e2 * at2));

            float f0 = xb0 + xr0 + wb * we0; f0 = f0 > 0.f ? f0 : 0.2f * f0;
            float f1 = xb1 + xr1 + wb * we1; f1 = f1 > 0.f ? f1 : 0.2f * f1;
            float f2 = xb2 + xr2 + wb * we2; f2 = f2 > 0.f ? f2 : 0.2f * f2;
            float tb = fmaf(f0, at0, fmaf(f1, at1, f2 * at2));

            #pragma unroll
            for (int o = 16; o > 0; o >>= 1) {
                ta += __shfl_xor_sync(FULLM, ta, o);
                tb += __shfl_xor_sync(FULLM, tb, o);
            }
            myal = (lane == j)     ? ta : myal;
            myal = (lane == j + 1) ? tb : myal;
        }
        if (j < cnt) {
            int   sa = __shfl_sync(FULLM, si, j);
            float wa = __shfl_sync(FULLM, wE, j);
            const float* xa = xlxr + (size_t)sa * 192;
            float xa0 = xa[lane], xa1 = xa[lane + 32], xa2 = xa[lane + 64];
            float e0 = xa0 + xr0 + wa * we0; e0 = e0 > 0.f ? e0 : 0.2f * e0;
            float e1 = xa1 + xr1 + wa * we1; e1 = e1 > 0.f ? e1 : 0.2f * e1;
            float e2 = xa2 + xr2 + wa * we2; e2 = e2 > 0.f ? e2 : 0.2f * e2;
            float ta = fmaf(e0, at0, fmaf(e1, at1, e2 * at2));
            #pragma unroll
            for (int o = 16; o > 0; o >>= 1) ta += __shfl_xor_sync(FULLM, ta, o);
            myal = (lane == j) ? ta : myal;
        }

        // ---- chunk-level online softmax merge
        float cm = wmax(myal);
        float nm = fmaxf(m, cm);
        float corr = __expf(m - nm);
        ssum *= corr; a0 *= corr; a1 *= corr; a2 *= corr;
        float wexp = (lane < cnt) ? __expf(myal - nm) : 0.f;
        ssum += wsum(wexp);
        m = nm;

        // ---- pass B: aggregation (rows L1-hot from pass A)
        int jj = 0;
        for (; jj + 4 <= cnt; jj += 4) {
            float w0 = __shfl_sync(FULLM, wexp, jj + 0);
            float w1 = __shfl_sync(FULLM, wexp, jj + 1);
            float w2 = __shfl_sync(FULLM, wexp, jj + 2);
            float w3 = __shfl_sync(FULLM, wexp, jj + 3);
            const float* x0p = xlxr + (size_t)__shfl_sync(FULLM, si, jj + 0) * 192;
            const float* x1p = xlxr + (size_t)__shfl_sync(FULLM, si, jj + 1) * 192;
            const float* x2p = xlxr + (size_t)__shfl_sync(FULLM, si, jj + 2) * 192;
            const float* x3p = xlxr + (size_t)__shfl_sync(FULLM, si, jj + 3) * 192;
            float v00 = x0p[lane], v01 = x0p[lane + 32], v02 = x0p[lane + 64];
            float v10 = x1p[lane], v11 = x1p[lane + 32], v12 = x1p[lane + 64];
            float v20 = x2p[lane], v21 = x2p[lane + 32], v22 = x2p[lane + 64];
            float v30 = x3p[lane], v31 = x3p[lane + 32], v32 = x3p[lane + 64];
            a0 = fmaf(w0, v00, a0); a1 = fmaf(w0, v01, a1); a2 = fmaf(w0, v02, a2);
            a0 = fmaf(w1, v10, a0); a1 = fmaf(w1, v11, a1); a2 = fmaf(w1, v12, a2);
            a0 = fmaf(w2, v20, a0); a1 = fmaf(w2, v21, a1); a2 = fmaf(w2, v22, a2);
            a0 = fmaf(w3, v30, a0); a1 = fmaf(w3, v31, a1); a2 = fmaf(w3, v32, a2);
        }
        for (; jj < cnt; jj++) {
            float w = __shfl_sync(FULLM, wexp, jj);
            const float* xp = xlxr + (size_t)__shfl_sync(FULLM, si, jj) * 192;
            a0 = fmaf(w, xp[lane],      a0);
            a1 = fmaf(w, xp[lane + 32], a1);
            a2 = fmaf(w, xp[lane + 64], a2);
        }
    }

    float inv = 1.0f / (ssum + 1e-16f);
    a0 *= inv; a1 *= inv; a2 *= inv;

    // ---- residual + bias + LayerNorm + ReLU
    size_t base = (size_t)n * HID;
    float x0 = g_h[base + lane]      + a0 + sBias[lane];
    float x1 = g_h[base + lane + 32] + a1 + sBias[lane + 32];
    float x2 = g_h[base + lane + 64] + a2 + sBias[lane + 64];
    g_h[base + lane]      = x0;
    g_h[base + lane + 32] = x1;
    g_h[base + lane + 64] = x2;

    float mean = wsum(x0 + x1 + x2) * (1.0f / HID);
    float d0 = x0 - mean, d1 = x1 - mean, d2 = x2 - mean;
    float rstd = rsqrtf(wsum(fmaf(d0, d0, fmaf(d1, d1, d2 * d2))) * (1.0f / HID) + 1e-5f);
    g_hn[base + lane]      = fmaxf(fmaf(d0 * rstd, sG[lane],      sB[lane]),      0.f);
    g_hn[base + lane + 32] = fmaxf(fmaf(d1 * rstd, sG[lane + 32], sB[lane + 32]), 0.f);
    g_hn[base + lane + 64] = fmaxf(fmaf(d2 * rstd, sG[lane + 64], sB[lane + 64]), 0.f);
}

// ---------------- final FC ----------------
__global__ void __launch_bounds__(256) fc_kernel(
    const float* __restrict__ fcW, const float* __restrict__ fcb,
    float* __restrict__ out)
{
    int warp = threadIdx.x >> 5;
    int lane = threadIdx.x & 31;
    int n = blockIdx.x * 8 + warp;
    if (n >= N_NODES) return;
    size_t base = (size_t)n * HID;
    float acc = fmaf(g_hn[base + lane], fcW[lane],
                fmaf(g_hn[base + lane + 32], fcW[lane + 32],
                     g_hn[base + lane + 64] * fcW[lane + 64]));
    acc = wsum(acc);
    if (lane == 0) out[n] = acc + fcb[0];
}

// ---------------- launch ----------------
extern "C" void kernel_launch(void* const* d_in, const int* in_sizes, int n_in,
                              void* d_out, int out_size)
{
    const float* x    = (const float*)d_in[0];
    const void*  ei   = (const void*) d_in[1];
    const float* ew   = (const float*)d_in[2];
    const float* encW = (const float*)d_in[3];
    const float* encb = (const float*)d_in[4];
    const float* Wl   = (const float*)d_in[5];
    const float* bl   = (const float*)d_in[6];
    const float* Wr   = (const float*)d_in[7];
    const float* br   = (const float*)d_in[8];
    const float* We   = (const float*)d_in[9];
    const float* att  = (const float*)d_in[10];
    const float* bias = (const float*)d_in[11];
    const float* lng  = (const float*)d_in[12];
    const float* lnb  = (const float*)d_in[13];
    const float* lnfg = (const float*)d_in[14];
    const float* lnfb = (const float*)d_in[15];
    const float* fcW  = (const float*)d_in[16];
    const float* fcb  = (const float*)d_in[17];
    float*       out  = (float*)d_out;

    void *p_h, *p_hn, *p_cnt, *p_x0, *p_x1;
    cudaGetSymbolAddress(&p_h,   g_h);
    cudaGetSymbolAddress(&p_hn,  g_hn);
    cudaGetSymbolAddress(&p_cnt, g_cnt);
    cudaGetSymbolAddress(&p_x0,  g_xlxr0);
    cudaGetSymbolAddress(&p_x1,  g_xlxr1);
    float* hbuf  = (float*)p_h;
    float* hnbuf = (float*)p_hn;
    float* xbuf[2] = { (float*)p_x0, (float*)p_x1 };

    // half-split block counts
    const int GEMM_A = NHALF / 64;                       // 391
    const int GEMM_B = (N_NODES - NHALF + 63) / 64;      // 391
    const int NODE_A = NHALF / 8;                        // 3128
    const int NODE_B = (N_NODES - NHALF + 7) / 8;        // 3122
    const int node_blocks  = (N_NODES + 7) / 8;          // 6250
    const int edge2_blocks = (E_EDGES / 2 + 255) / 256;  // 1563

    cudaStream_t s2, s3;
    cudaStreamCreateWithFlags(&s2, cudaStreamNonBlocking);
    cudaStreamCreateWithFlags(&s3, cudaStreamNonBlocking);
    cudaEvent_t evFork, evCSR, evEncA, evGA[L_LAYERS], evGatA[L_LAYERS];
    cudaEventCreateWithFlags(&evFork, cudaEventDisableTiming);
    cudaEventCreateWithFlags(&evCSR,  cudaEventDisableTiming);
    cudaEventCreateWithFlags(&evEncA, cudaEventDisableTiming);
    for (int i = 0; i < L_LAYERS; i++) {
        cudaEventCreateWithFlags(&evGA[i],   cudaEventDisableTiming);
        cudaEventCreateWithFlags(&evGatA[i], cudaEventDisableTiming);
    }

    // ---- fork both side streams off the capture stream ----
    cudaEventRecord(evFork, 0);
    cudaStreamWaitEvent(s2, evFork, 0);
    cudaStreamWaitEvent(s3, evFork, 0);

    // ---- s2: CSR build (independent of features) ----
    detect_kernel<<<1, 1, 0, s2>>>((const int*)ei);
    cudaMemsetAsync(p_cnt, 0, N_NODES * sizeof(int), s2);
    hist_kernel<<<edge2_blocks, 256, 0, s2>>>(ei);
    scan_kernel<<<1, 1024, 0, s2>>>();
    scatter_kernel<<<edge2_blocks, 256, 0, s2>>>(ei, ew);
    cudaEventRecord(evCSR, s2);

    // ---- main: enc(A) ; s3: ln(A) + g0(A) ; main: enc(B) + ln(B) + g0(B) ----
    gemm2_kernel<F_IN, HID, HID, 16><<<GEMM_A, 256>>>(
        x, encW, encW, encb, encb, hbuf, 0, NHALF);
    cudaEventRecord(evEncA, 0);

    cudaStreamWaitEvent(s3, evEncA, 0);
    ln_init_kernel<<<NODE_A, 256, 0, s3>>>(hbuf, lng, lnb, hnbuf, 0, NHALF);
    gemm2_kernel<HID, 2 * HID, HID, 32><<<GEMM_A, 256, 0, s3>>>(
        hnbuf, Wl, Wr, bl, br, xbuf[0], 0, NHALF);
    cudaEventRecord(evGA[0], s3);

    gemm2_kernel<F_IN, HID, HID, 16><<<GEMM_B, 256>>>(
        x, encW, encW, encb, encb, hbuf, NHALF, N_NODES);
    ln_init_kernel<<<NODE_B, 256>>>(hbuf, lng, lnb, hnbuf, NHALF, N_NODES);
    gemm2_kernel<HID, 2 * HID, HID, 32><<<GEMM_B, 256>>>(
        hnbuf, Wl, Wr, bl, br, xbuf[0], NHALF, N_NODES);

    // join for gat0: g0 full + CSR
    cudaStreamWaitEvent(0, evGA[0], 0);
    cudaStreamWaitEvent(0, evCSR, 0);

    // ---- pipelined layer loop ----
    for (int i = 0; i < L_LAYERS; i++) {
        const float* gnext = (i < L_LAYERS - 1) ? (lng + (i + 1) * HID) : lnfg;
        const float* bnext = (i < L_LAYERS - 1) ? (lnb + (i + 1) * HID) : lnfb;
        float* xb_cur = xbuf[i & 1];

        // gat_i(A) on main
        gat_fused_kernel<<<NODE_A, 256>>>(
            xb_cur, We + i * HID, att + i * HID, bias + i * HID, gnext, bnext,
            0, NHALF);
        cudaEventRecord(evGatA[i], 0);

        if (i + 1 < L_LAYERS) {
            float* xb_nxt = xbuf[(i + 1) & 1];
            // s3: gemm_{i+1}(A) overlaps gat_i(B); double buffer avoids races
            cudaStreamWaitEvent(s3, evGatA[i], 0);
            gemm2_kernel<HID, 2 * HID, HID, 32><<<GEMM_A, 256, 0, s3>>>(
                hnbuf, Wl + (size_t)(i + 1) * HID * HID, Wr + (size_t)(i + 1) * HID * HID,
                bl + (i + 1) * HID, br + (i + 1) * HID, xb_nxt, 0, NHALF);
            cudaEventRecord(evGA[i + 1], s3);

            // main: gat_i(B), then gemm_{i+1}(B), then join gemm_{i+1}(A)
            gat_fused_kernel<<<NODE_B, 256>>>(
                xb_cur, We + i * HID, att + i * HID, bias + i * HID, gnext, bnext,
                NHALF, N_NODES);
            gemm2_kernel<HID, 2 * HID, HID, 32><<<GEMM_B, 256>>>(
                hnbuf, Wl + (size_t)(i + 1) * HID * HID, Wr + (size_t)(i + 1) * HID * HID,
                bl + (i + 1) * HID, br + (i + 1) * HID, xb_nxt, NHALF, N_NODES);
            cudaStreamWaitEvent(0, evGA[i + 1], 0);
        } else {
            // last layer: just finish the B half
            gat_fused_kernel<<<NODE_B, 256>>>(
                xb_cur, We + i * HID, att + i * HID, bias + i * HID, gnext, bnext,
                NHALF, N_NODES);
        }
    }

    fc_kernel<<<node_blocks, 256>>>(fcW, fcb, out);

    cudaEventDestroy(evFork);
    cudaEventDestroy(evCSR);
    cudaEventDestroy(evEncA);
    for (int i = 0; i < L_LAYERS; i++) {
        cudaEventDestroy(evGA[i]);
        cudaEventDestroy(evGatA[i]);
    }
    cudaStreamDestroy(s2);
    cudaStreamDestroy(s3);
}

// round 11
// speedup vs baseline: 1.2426x; 1.0201x over previous
#include <cuda_runtime.h>
#include <cuda_bf16.h>
#include <cstdint>
#include <math.h>

#define N_NODES 50000
#define NHALF   25024          // multiple of 64 and 8
#define E_EDGES 800000
#define F_IN    128
#define HID     96
#define L_LAYERS 4
#define FULLM 0xffffffffu

// ---------------- device scratch ----------------
__device__ __align__(16) float g_h    [N_NODES * HID];
__device__ __align__(16) float g_hn   [N_NODES * HID];
__device__ __align__(16) float g_xlxr0[N_NODES * 2 * HID];  // ping
__device__ __align__(16) float g_xlxr1[N_NODES * 2 * HID];  // pong
__device__ __align__(16) int   g_cnt   [N_NODES];
__device__ __align__(16) int   g_rowptr[N_NODES + 1];
__device__ __align__(16) int   g_cursor[N_NODES];
__device__ __align__(16) int2  g_edge  [E_EDGES];   // (src, ew bits), sorted by dst
__device__ int g_is64;

// bf16 weight images, n-major [CW][K]: enc 96x128 @0; layer i 192x96 @ 12288 + i*18432
#define BW_ENC_OFF 0
#define BW_LAY_OFF 12288
#define BW_TOTAL   (12288 + 4 * 18432)
__device__ __align__(16) unsigned short g_bw_hi[BW_TOTAL];
__device__ __align__(16) unsigned short g_bw_lo[BW_TOTAL];

// ---------------- edge_index dtype sniff ----------------
__global__ void detect_kernel(const int* ei32) {
    bool is64 = true;
    #pragma unroll
    for (int i = 0; i < 8; i++) if (ei32[2 * i + 1] != 0) is64 = false;
    g_is64 = is64 ? 1 : 0;
}

__device__ __forceinline__ void load_edge(const void* ei, int e, int& s, int& d) {
    if (g_is64) {
        const long long* p = (const long long*)ei;
        s = (int)p[e]; d = (int)p[E_EDGES + e];
    } else {
        const int* p = (const int*)ei;
        s = p[e]; d = p[E_EDGES + e];
    }
}

// ---------------- CSR build ----------------
__global__ void __launch_bounds__(256) hist_kernel(const void* ei) {
    int base = (blockIdx.x * blockDim.x + threadIdx.x) * 2;
    #pragma unroll
    for (int i = 0; i < 2; i++) {
        int e = base + i;
        if (e < E_EDGES) {
            int s, d; load_edge(ei, e, s, d);
            atomicAdd(&g_cnt[d], 1);
        }
    }
}

__global__ void __launch_bounds__(1024) scan_kernel() {
    __shared__ int ps[1024];
    int t = threadIdx.x;
    const int CH = (N_NODES + 1023) / 1024;
    int base = t * CH;
    int sum = 0;
    for (int i = 0; i < CH; i++) {
        int idx = base + i;
        if (idx < N_NODES) sum += g_cnt[idx];
    }
    ps[t] = sum;
    __syncthreads();
    for (int off = 1; off < 1024; off <<= 1) {
        int v = (t >= off) ? ps[t - off] : 0;
        __syncthreads();
        ps[t] += v;
        __syncthreads();
    }
    int run = ps[t] - sum;
    for (int i = 0; i < CH; i++) {
        int idx = base + i;
        if (idx < N_NODES) {
            g_rowptr[idx] = run;
            g_cursor[idx] = run;
            run += g_cnt[idx];
        }
    }
    if (t == 0) g_rowptr[N_NODES] = E_EDGES;
}

__global__ void __launch_bounds__(256) scatter_kernel(const void* ei, const float* __restrict__ ew) {
    int base = (blockIdx.x * blockDim.x + threadIdx.x) * 2;
    #pragma unroll
    for (int i = 0; i < 2; i++) {
        int e = base + i;
        if (e < E_EDGES) {
            int s, d; load_edge(ei, e, s, d);
            int p = atomicAdd(&g_cursor[d], 1);
            g_edge[p] = make_int2(s, __float_as_int(ew[e]));
        }
    }
}

// ---------------- prep: transpose + bf16-split weights into n-major images ----------------
__global__ void __launch_bounds__(256) prep_w_kernel(
    const float* __restrict__ encW, const float* __restrict__ Wl, const float* __restrict__ Wr)
{
    int idx = blockIdx.x * blockDim.x + threadIdx.x;
    if (idx >= BW_TOTAL) return;
    float v; int dest;
    if (idx < 12288) {                 // enc: [96][128]
        int n = idx >> 7, k = idx & 127;
        v = encW[k * HID + n];
        dest = n * 128 + k;
    } else {
        int r = idx - 12288;
        int i = r / 18432; r -= i * 18432;
        int n = r / HID, k = r % HID;  // [192][96]
        v = (n < HID) ? Wl[(size_t)i * HID * HID + k * HID + n]
                      : Wr[(size_t)i * HID * HID + k * HID + (n - HID)];
        dest = BW_LAY_OFF + i * 18432 + n * HID + k;
    }
    __nv_bfloat16 hi = __float2bfloat16(v);
    float lof = v - __bfloat162float(hi);
    __nv_bfloat16 lo = __float2bfloat16(lof);
    g_bw_hi[dest] = *(unsigned short*)&hi;
    g_bw_lo[dest] = *(unsigned short*)&lo;
}

// ---------------- tensor-core GEMM via mma.sync (sm_80-class bf16 HMMA) ----------------
// C[rbeg:rend, CW] = A @ W^T + bias. 3-term split-bf16 for fp32-grade precision.
// Block: 64 rows x CW cols, 256 threads (8 warps = 2M x 4N), warp tile 32 x WN.
// A staged in smem (hi/lo, padded, conflict-free); B fragments read from global
// bf16 images (<=36 KB -> L1-resident). Plain 32-bit fragment loads, no ldmatrix.
__device__ __forceinline__ void mma16816(
    float& c0, float& c1, float& c2, float& c3,
    uint32_t a0, uint32_t a1, uint32_t a2, uint32_t a3,
    uint32_t b0, uint32_t b1)
{
    asm volatile(
        "mma.sync.aligned.m16n8k16.row.col.f32.bf16.bf16.f32 "
        "{%0,%1,%2,%3}, {%4,%5,%6,%7}, {%8,%9}, {%0,%1,%2,%3};"
        : "+f"(c0), "+f"(c1), "+f"(c2), "+f"(c3)
        : "r"(a0), "r"(a1), "r"(a2), "r"(a3), "r"(b0), "r"(b1));
}

template <int K, int CW, int CW1, int WN>
__global__ void __launch_bounds__(256) gemm_mma_kernel(
    const float* __restrict__ A,
    const unsigned short* __restrict__ Bhi, const unsigned short* __restrict__ Blo,
    const float* __restrict__ b1v, const float* __restrict__ b2v,
    float* __restrict__ C, int rbeg, int rend)
{
    constexpr int NS  = K / 16;       // k-steps
    constexpr int NF  = WN / 8;       // n-frags per warp
    constexpr int SWD = K / 2 + 4;    // smem row stride in words (pad 8 bf16)

    __shared__ uint32_t Ah[64 * SWD];
    __shared__ uint32_t Al[64 * SWD];

    const int tid  = threadIdx.x;
    const int wid  = tid >> 5;
    const int lane = tid & 31;
    const int g    = lane >> 2;
    const int t    = lane & 3;
    const int warp_m = wid >> 2;      // 0..1
    const int warp_n = wid & 3;       // 0..3
    const int rowbase = rbeg + blockIdx.x * 64;

    // ---- stage A (fp32 -> bf16 hi/lo) ----
    for (int i = tid; i < 64 * (K / 4); i += 256) {
        int row = i / (K / 4);
        int kq  = (i % (K / 4)) * 4;
        float4 v = make_float4(0.f, 0.f, 0.f, 0.f);
        int grow = rowbase + row;
        if (grow < rend) v = *(const float4*)(A + (size_t)grow * K + kq);
        __nv_bfloat162 h01 = __floats2bfloat162_rn(v.x, v.y);
        __nv_bfloat162 h23 = __floats2bfloat162_rn(v.z, v.w);
        __nv_bfloat162 l01 = __floats2bfloat162_rn(v.x - __bfloat162float(h01.x),
                                                   v.y - __bfloat162float(h01.y));
        __nv_bfloat162 l23 = __floats2bfloat162_rn(v.z - __bfloat162float(h23.x),
                                                   v.w - __bfloat162float(h23.y));
        int base = row * SWD + (kq >> 1);
        Ah[base]     = *(uint32_t*)&h01;
        Ah[base + 1] = *(uint32_t*)&h23;
        Al[base]     = *(uint32_t*)&l01;
        Al[base + 1] = *(uint32_t*)&l23;
    }
    __syncthreads();

    const uint32_t* BwH = (const uint32_t*)Bhi;
    const uint32_t* BwL = (const uint32_t*)Blo;

    float c[2][NF][4];
    #pragma unroll
    for (int mf = 0; mf < 2; mf++)
        #pragma unroll
        for (int nf = 0; nf < NF; nf++)
            #pragma unroll
            for (int q = 0; q < 4; q++) c[mf][nf][q] = 0.f;

    // ---- 3 split terms: Ah*Bh, Ah*Bl, Al*Bh ----
    #pragma unroll
    for (int s = 0; s < 3; s++) {
        const uint32_t* Aimg = (s < 2) ? Ah : Al;
        const uint32_t* Bimg = (s == 1) ? BwL : BwH;
        #pragma unroll
        for (int ks = 0; ks < NS; ks++) {
            uint32_t a[2][4];
            #pragma unroll
            for (int mf = 0; mf < 2; mf++) {
                int r0 = warp_m * 32 + mf * 16 + g;
                int wi = r0 * SWD + ks * 8 + t;
                a[mf][0] = Aimg[wi];
                a[mf][1] = Aimg[wi + 8 * SWD];
                a[mf][2] = Aimg[wi + 4];
                a[mf][3] = Aimg[wi + 8 * SWD + 4];
            }
            #pragma unroll
            for (int nf = 0; nf < NF; nf++) {
                int n = warp_n * WN + nf * 8 + g;
                int bw = n * (K / 2) + ks * 8 + t;
                uint32_t b0 = __ldg(&Bimg[bw]);
                uint32_t b1 = __ldg(&Bimg[bw + 4]);
                #pragma unroll
                for (int mf = 0; mf < 2; mf++)
                    mma16816(c[mf][nf][0], c[mf][nf][1], c[mf][nf][2], c[mf][nf][3],
                             a[mf][0], a[mf][1], a[mf][2], a[mf][3], b0, b1);
            }
        }
    }

    // ---- epilogue: bias + store ----
    #pragma unroll
    for (int nf = 0; nf < NF; nf++) {
        int col = warp_n * WN + nf * 8 + 2 * t;
        float bv0 = (col < CW1) ? b1v[col] : b2v[col - CW1];
        float bv1 = (col + 1 < CW1) ? b1v[col + 1] : b2v[col + 1 - CW1];
        #pragma unroll
        for (int mf = 0; mf < 2; mf++) {
            int row = rowbase + warp_m * 32 + mf * 16 + g;
            if (row < rend)
                *(float2*)(C + (size_t)row * CW + col) =
                    make_float2(c[mf][nf][0] + bv0, c[mf][nf][1] + bv1);
            if (row + 8 < rend)
                *(float2*)(C + (size_t)(row + 8) * CW + col) =
                    make_float2(c[mf][nf][2] + bv0, c[mf][nf][3] + bv1);
        }
    }
}

// ---------------- warp reduce ----------------
__device__ __forceinline__ float wsum(float v) {
    #pragma unroll
    for (int o = 16; o > 0; o >>= 1) v += __shfl_xor_sync(FULLM, v, o);
    return v;
}
__device__ __forceinline__ float wmax(float v) {
    #pragma unroll
    for (int o = 16; o > 0; o >>= 1) v = fmaxf(v, __shfl_xor_sync(FULLM, v, o));
    return v;
}

// ---------------- initial LayerNorm + ReLU (h -> hn), range-parameterized ----------------
__global__ void __launch_bounds__(256) ln_init_kernel(
    const float* __restrict__ h,
    const float* __restrict__ g, const float* __restrict__ b,
    float* __restrict__ hn, int nbeg, int nend)
{
    int warp = threadIdx.x >> 5;
    int lane = threadIdx.x & 31;
    int n = nbeg + blockIdx.x * 8 + warp;
    if (n >= nend) return;
    size_t base = (size_t)n * HID;

    float v0 = h[base + lane], v1 = h[base + lane + 32], v2 = h[base + lane + 64];
    float mean = wsum(v0 + v1 + v2) * (1.0f / HID);
    float d0 = v0 - mean, d1 = v1 - mean, d2 = v2 - mean;
    float rstd = rsqrtf(wsum(fmaf(d0, d0, fmaf(d1, d1, d2 * d2))) * (1.0f / HID) + 1e-5f);
    hn[base + lane]      = fmaxf(fmaf(d0 * rstd, g[lane],      b[lane]),      0.f);
    hn[base + lane + 32] = fmaxf(fmaf(d1 * rstd, g[lane + 32], b[lane + 32]), 0.f);
    hn[base + lane + 64] = fmaxf(fmaf(d2 * rstd, g[lane + 64], b[lane + 64]), 0.f);
}

// ---------------- fused GAT layer (R4-proven body; xlxr pointer + range params) ----------
__global__ void __launch_bounds__(256) gat_fused_kernel(
    const float* __restrict__ xlxr,
    const float* __restrict__ We,  const float* __restrict__ att,
    const float* __restrict__ bias,
    const float* __restrict__ lg,  const float* __restrict__ lb,
    int nbeg, int nend)
{
    __shared__ float sWe[HID], sAtt[HID], sBias[HID], sG[HID], sB[HID];
    int t = threadIdx.x;
    if (t < HID) {
        sWe[t] = We[t]; sAtt[t] = att[t]; sBias[t] = bias[t];
        sG[t] = lg[t];  sB[t]  = lb[t];
    }
    __syncthreads();

    int warp = t >> 5, lane = t & 31;
    int n = nbeg + blockIdx.x * 8 + warp;
    if (n >= nend) return;

    int r0 = g_rowptr[n], r1 = g_rowptr[n + 1];
    const float* xrp = xlxr + (size_t)n * 192 + 96;
    float xr0 = xrp[lane], xr1 = xrp[lane + 32], xr2 = xrp[lane + 64];
    float we0 = sWe[lane],  we1 = sWe[lane + 32],  we2 = sWe[lane + 64];
    float at0 = sAtt[lane], at1 = sAtt[lane + 32], at2 = sAtt[lane + 64];

    float m = -INFINITY, ssum = 0.f;
    float a0 = 0.f, a1 = 0.f, a2 = 0.f;

    for (int c0 = r0; c0 < r1; c0 += 32) {
        int cnt = min(32, r1 - c0);
        int p = c0 + lane;
        int   si = 0;
        float wE = 0.f;
        if (lane < cnt) {
            int2 ed = g_edge[p];
            si = ed.x;
            wE = __int_as_float(ed.y);
        }

        // ---- pass A: alpha per edge (coalesced row loads, independent reduces)
        float myal = -INFINITY;
        int j = 0;
        for (; j + 2 <= cnt; j += 2) {
            int   sa = __shfl_sync(FULLM, si, j);
            int   sb = __shfl_sync(FULLM, si, j + 1);
            float wa = __shfl_sync(FULLM, wE, j);
            float wb = __shfl_sync(FULLM, wE, j + 1);
            const float* xa = xlxr + (size_t)sa * 192;
            const float* xb = xlxr + (size_t)sb * 192;
            float xa0 = xa[lane], xa1 = xa[lane + 32], xa2 = xa[lane + 64];
            float xb0 = xb[lane], xb1 = xb[lane + 32], xb2 = xb[lane + 64];

            float e0 = xa0 + xr0 + wa * we0; e0 = e0 > 0.f ? e0 : 0.2f * e0;
            float e1 = xa1 + xr1 + wa * we1; e1 = e1 > 0.f ? e1 : 0.2f * e1;
            float e2 = xa2 + xr2 + wa * we2; e2 = e2 > 0.f ? e2 : 0.2f * e2;
            float ta = fmaf(e0, at0, fmaf(e1, at1, e2 * at2));

            float f0 = xb0 + xr0 + wb * we0; f0 = f0 > 0.f ? f0 : 0.2f * f0;
            float f1 = xb1 + xr1 + wb * we1; f1 = f1 > 0.f ? f1 : 0.2f * f1;
            float f2 = xb2 + xr2 + wb * we2; f2 = f2 > 0.f ? f2 : 0.2f * f2;
            float tb = fmaf(f0, at0, fmaf(f1, at1, f2 * at2));

            #pragma unroll
            for (int o = 16; o > 0; o >>= 1) {
                ta += __shfl_xor_sync(FULLM, ta, o);
                tb += __shfl_xor_sync(FULLM, tb, o);
            }
            myal = (lane == j)     ? ta : myal;
            myal = (lane == j + 1) ? tb : myal;
        }
        if (j < cnt) {
            int   sa = __shfl_sync(FULLM, si, j);
            float wa = __shfl_sync(FULLM, wE, j);
            const float* xa = xlxr + (size_t)sa * 192;
            float xa0 = xa[lane], xa1 = xa[lane + 32], xa2 = xa[lane + 64];
            float e0 = xa0 + xr0 + wa * we0; e0 = e0 > 0.f ? e0 : 0.2f * e0;
            float e1 = xa1 + xr1 + wa * we1; e1 = e1 > 0.f ? e1 : 0.2f * e1;
            float e2 = xa2 + xr2 + wa * we2; e2 = e2 > 0.f ? e2 : 0.2f * e2;
            float ta = fmaf(e0, at0, fmaf(e1, at1, e2 * at2));
            #pragma unroll
            for (int o = 16; o > 0; o >>= 1) ta += __shfl_xor_sync(FULLM, ta, o);
            myal = (lane == j) ? ta : myal;
        }

        // ---- chunk-level online softmax merge
        float cm = wmax(myal);
        float nm = fmaxf(m, cm);
        float corr = __expf(m - nm);
        ssum *= corr; a0 *= corr; a1 *= corr; a2 *= corr;
        float wexp = (lane < cnt) ? __expf(myal - nm) : 0.f;
        ssum += wsum(wexp);
        m = nm;

        // ---- pass B: aggregation (rows L1-hot from pass A)
        int jj = 0;
        for (; jj + 4 <= cnt; jj += 4) {
            float w0 = __shfl_sync(FULLM, wexp, jj + 0);
            float w1 = __shfl_sync(FULLM, wexp, jj + 1);
            float w2 = __shfl_sync(FULLM, wexp, jj + 2);
            float w3 = __shfl_sync(FULLM, wexp, jj + 3);
            const float* x0p = xlxr + (size_t)__shfl_sync(FULLM, si, jj + 0) * 192;
            const float* x1p = xlxr + (size_t)__shfl_sync(FULLM, si, jj + 1) * 192;
            const float* x2p = xlxr + (size_t)__shfl_sync(FULLM, si, jj + 2) * 192;
            const float* x3p = xlxr + (size_t)__shfl_sync(FULLM, si, jj + 3) * 192;
            float v00 = x0p[lane], v01 = x0p[lane + 32], v02 = x0p[lane + 64];
            float v10 = x1p[lane], v11 = x1p[lane + 32], v12 = x1p[lane + 64];
            float v20 = x2p[lane], v21 = x2p[lane + 32], v22 = x2p[lane + 64];
            float v30 = x3p[lane], v31 = x3p[lane + 32], v32 = x3p[lane + 64];
            a0 = fmaf(w0, v00, a0); a1 = fmaf(w0, v01, a1); a2 = fmaf(w0, v02, a2);
            a0 = fmaf(w1, v10, a0); a1 = fmaf(w1, v11, a1); a2 = fmaf(w1, v12, a2);
            a0 = fmaf(w2, v20, a0); a1 = fmaf(w2, v21, a1); a2 = fmaf(w2, v22, a2);
            a0 = fmaf(w3, v30, a0); a1 = fmaf(w3, v31, a1); a2 = fmaf(w3, v32, a2);
        }
        for (; jj < cnt; jj++) {
            float w = __shfl_sync(FULLM, wexp, jj);
            const float* xp = xlxr + (size_t)__shfl_sync(FULLM, si, jj) * 192;
            a0 = fmaf(w, xp[lane],      a0);
            a1 = fmaf(w, xp[lane + 32], a1);
            a2 = fmaf(w, xp[lane + 64], a2);
        }
    }

    float inv = 1.0f / (ssum + 1e-16f);
    a0 *= inv; a1 *= inv; a2 *= inv;

    // ---- residual + bias + LayerNorm + ReLU
    size_t base = (size_t)n * HID;
    float x0 = g_h[base + lane]      + a0 + sBias[lane];
    float x1 = g_h[base + lane + 32] + a1 + sBias[lane + 32];
    float x2 = g_h[base + lane + 64] + a2 + sBias[lane + 64];
    g_h[base + lane]      = x0;
    g_h[base + lane + 32] = x1;
    g_h[base + lane + 64] = x2;

    float mean = wsum(x0 + x1 + x2) * (1.0f / HID);
    float d0 = x0 - mean, d1 = x1 - mean, d2 = x2 - mean;
    float rstd = rsqrtf(wsum(fmaf(d0, d0, fmaf(d1, d1, d2 * d2))) * (1.0f / HID) + 1e-5f);
    g_hn[base + lane]      = fmaxf(fmaf(d0 * rstd, sG[lane],      sB[lane]),      0.f);
    g_hn[base + lane + 32] = fmaxf(fmaf(d1 * rstd, sG[lane + 32], sB[lane + 32]), 0.f);
    g_hn[base + lane + 64] = fmaxf(fmaf(d2 * rstd, sG[lane + 64], sB[lane + 64]), 0.f);
}

// ---------------- final FC ----------------
__global__ void __launch_bounds__(256) fc_kernel(
    const float* __restrict__ fcW, const float* __restrict__ fcb,
    float* __restrict__ out)
{
    int warp = threadIdx.x >> 5;
    int lane = threadIdx.x & 31;
    int n = blockIdx.x * 8 + warp;
    if (n >= N_NODES) return;
    size_t base = (size_t)n * HID;
    float acc = fmaf(g_hn[base + lane], fcW[lane],
                fmaf(g_hn[base + lane + 32], fcW[lane + 32],
                     g_hn[base + lane + 64] * fcW[lane + 64]));
    acc = wsum(acc);
    if (lane == 0) out[n] = acc + fcb[0];
}

// ---------------- launch ----------------
extern "C" void kernel_launch(void* const* d_in, const int* in_sizes, int n_in,
                              void* d_out, int out_size)
{
    const float* x    = (const float*)d_in[0];
    const void*  ei   = (const void*) d_in[1];
    const float* ew   = (const float*)d_in[2];
    const float* encW = (const float*)d_in[3];
    const float* encb = (const float*)d_in[4];
    const float* Wl   = (const float*)d_in[5];
    const float* bl   = (const float*)d_in[6];
    const float* Wr   = (const float*)d_in[7];
    const float* br   = (const float*)d_in[8];
    const float* We   = (const float*)d_in[9];
    const float* att  = (const float*)d_in[10];
    const float* bias = (const float*)d_in[11];
    const float* lng  = (const float*)d_in[12];
    const float* lnb  = (const float*)d_in[13];
    const float* lnfg = (const float*)d_in[14];
    const float* lnfb = (const float*)d_in[15];
    const float* fcW  = (const float*)d_in[16];
    const float* fcb  = (const float*)d_in[17];
    float*       out  = (float*)d_out;

    void *p_h, *p_hn, *p_cnt, *p_x0, *p_x1, *p_bh, *p_bl;
    cudaGetSymbolAddress(&p_h,   g_h);
    cudaGetSymbolAddress(&p_hn,  g_hn);
    cudaGetSymbolAddress(&p_cnt, g_cnt);
    cudaGetSymbolAddress(&p_x0,  g_xlxr0);
    cudaGetSymbolAddress(&p_x1,  g_xlxr1);
    cudaGetSymbolAddress(&p_bh,  g_bw_hi);
    cudaGetSymbolAddress(&p_bl,  g_bw_lo);
    float* hbuf  = (float*)p_h;
    float* hnbuf = (float*)p_hn;
    float* xbuf[2] = { (float*)p_x0, (float*)p_x1 };
    const unsigned short* bwh = (const unsigned short*)p_bh;
    const unsigned short* bwl = (const unsigned short*)p_bl;

    const int GEMM_A = NHALF / 64;                       // 391
    const int GEMM_B = (N_NODES - NHALF + 63) / 64;      // 391
    const int NODE_A = NHALF / 8;
    const int NODE_B = (N_NODES - NHALF + 7) / 8;
    const int node_blocks  = (N_NODES + 7) / 8;
    const int edge2_blocks = (E_EDGES / 2 + 255) / 256;
    const int prep_blocks  = (BW_TOTAL + 255) / 256;

    cudaStream_t s2, s3;
    cudaStreamCreateWithFlags(&s2, cudaStreamNonBlocking);
    cudaStreamCreateWithFlags(&s3, cudaStreamNonBlocking);
    cudaEvent_t evFork, evCSR, evEncA, evGA[L_LAYERS], evGatA[L_LAYERS];
    cudaEventCreateWithFlags(&evFork, cudaEventDisableTiming);
    cudaEventCreateWithFlags(&evCSR,  cudaEventDisableTiming);
    cudaEventCreateWithFlags(&evEncA, cudaEventDisableTiming);
    for (int i = 0; i < L_LAYERS; i++) {
        cudaEventCreateWithFlags(&evGA[i],   cudaEventDisableTiming);
        cudaEventCreateWithFlags(&evGatA[i], cudaEventDisableTiming);
    }

    cudaEventRecord(evFork, 0);
    cudaStreamWaitEvent(s2, evFork, 0);
    cudaStreamWaitEvent(s3, evFork, 0);

    // ---- s2: CSR build ----
    detect_kernel<<<1, 1, 0, s2>>>((const int*)ei);
    cudaMemsetAsync(p_cnt, 0, N_NODES * sizeof(int), s2);
    hist_kernel<<<edge2_blocks, 256, 0, s2>>>(ei);
    scan_kernel<<<1, 1024, 0, s2>>>();
    scatter_kernel<<<edge2_blocks, 256, 0, s2>>>(ei, ew);
    cudaEventRecord(evCSR, s2);

    // ---- main: weight prep, then enc(A) ----
    prep_w_kernel<<<prep_blocks, 256>>>(encW, Wl, Wr);
    gemm_mma_kernel<F_IN, HID, HID, 24><<<GEMM_A, 256>>>(
        x, bwh + BW_ENC_OFF, bwl + BW_ENC_OFF, encb, encb, hbuf, 0, NHALF);
    cudaEventRecord(evEncA, 0);

    cudaStreamWaitEvent(s3, evEncA, 0);
    ln_init_kernel<<<NODE_A, 256, 0, s3>>>(hbuf, lng, lnb, hnbuf, 0, NHALF);
    gemm_mma_kernel<HID, 2 * HID, HID, 48><<<GEMM_A, 256, 0, s3>>>(
        hnbuf, bwh + BW_LAY_OFF, bwl + BW_LAY_OFF, bl, br, xbuf[0], 0, NHALF);
    cudaEventRecord(evGA[0], s3);

    gemm_mma_kernel<F_IN, HID, HID, 24><<<GEMM_B, 256>>>(
        x, bwh + BW_ENC_OFF, bwl + BW_ENC_OFF, encb, encb, hbuf, NHALF, N_NODES);
    ln_init_kernel<<<NODE_B, 256>>>(hbuf, lng, lnb, hnbuf, NHALF, N_NODES);
    gemm_mma_kernel<HID, 2 * HID, HID, 48><<<GEMM_B, 256>>>(
        hnbuf, bwh + BW_LAY_OFF, bwl + BW_LAY_OFF, bl, br, xbuf[0], NHALF, N_NODES);

    cudaStreamWaitEvent(0, evGA[0], 0);
    cudaStreamWaitEvent(0, evCSR, 0);

    // ---- pipelined layer loop ----
    for (int i = 0; i < L_LAYERS; i++) {
        const float* gnext = (i < L_LAYERS - 1) ? (lng + (i + 1) * HID) : lnfg;
        const float* bnext = (i < L_LAYERS - 1) ? (lnb + (i + 1) * HID) : lnfb;
        float* xb_cur = xbuf[i & 1];

        gat_fused_kernel<<<NODE_A, 256>>>(
            xb_cur, We + i * HID, att + i * HID, bias + i * HID, gnext, bnext,
            0, NHALF);
        cudaEventRecord(evGatA[i], 0);

        if (i + 1 < L_LAYERS) {
            float* xb_nxt = xbuf[(i + 1) & 1];
            cudaStreamWaitEvent(s3, evGatA[i], 0);
            gemm_mma_kernel<HID, 2 * HID, HID, 48><<<GEMM_A, 256, 0, s3>>>(
                hnbuf, bwh + BW_LAY_OFF + (i + 1) * 18432, bwl + BW_LAY_OFF + (i + 1) * 18432,
                bl + (i + 1) * HID, br + (i + 1) * HID, xb_nxt, 0, NHALF);
            cudaEventRecord(evGA[i + 1], s3);

            gat_fused_kernel<<<NODE_B, 256>>>(
                xb_cur, We + i * HID, att + i * HID, bias + i * HID, gnext, bnext,
                NHALF, N_NODES);
            gemm_mma_kernel<HID, 2 * HID, HID, 48><<<GEMM_B, 256>>>(
                hnbuf, bwh + BW_LAY_OFF + (i + 1) * 18432, bwl + BW_LAY_OFF + (i + 1) * 18432,
                bl + (i + 1) * HID, br + (i + 1) * HID, xb_nxt, NHALF, N_NODES);
            cudaStreamWaitEvent(0, evGA[i + 1], 0);
        } else {
            gat_fused_kernel<<<NODE_B, 256>>>(
                xb_cur, We + i * HID, att + i * HID, bias + i * HID, gnext, bnext,
                NHALF, N_NODES);
        }
    }

    fc_kernel<<<node_blocks, 256>>>(fcW, fcb, out);

    cudaEventDestroy(evFork);
    cudaEventDestroy(evCSR);
    cudaEventDestroy(evEncA);
    for (int i = 0; i < L_LAYERS; i++) {
        cudaEventDestroy(evGA[i]);
        cudaEventDestroy(evGatA[i]);
    }
    cudaStreamDestroy(s2);
    cudaStreamDestroy(s3);
}